// round 13
// baseline (speedup 1.0000x reference)
#include <cuda_runtime.h>
#include <cuda_bf16.h>
#include <cuda_fp16.h>
#include <math.h>

// Problem constants
#define NB 8        // batch
#define C 256       // channels
#define HW 1024     // 32*32
#define NH 32       // heads
#define HD 8        // head dim
#define NG 8        // groupnorm groups
#define CG 32       // channels per group
#define GN_EPS 1e-5f

// Scratch (allocation-free rule: __device__ globals)
__device__ __half g_qkvh[(size_t)NB * 3 * C * HW]; // 12 MB (fp16 qkv)
__device__ __half g_yh[(size_t)NB * C * HW];       // 4 MB (fp16 y)
__device__ float  g_A[NB * C];                     // per-(n,c) GN scale
__device__ float  g_B[NB * C];                     // per-(n,c) GN shift
__device__ float  g_part[NB * NG * 8 * 2];         // GN partial sums

typedef unsigned int uint;

// ---------------------------------------------------------------------------
// fp16 / mma helpers
// ---------------------------------------------------------------------------
__device__ __forceinline__ uint cvt_f16x2(float lo, float hi) {
    uint r;
    asm("cvt.rn.f16x2.f32 %0, %1, %2;" : "=r"(r) : "f"(hi), "f"(lo));
    return r;
}
__device__ __forceinline__ uint ex2_f16x2(uint x) {
    uint r;
    asm("ex2.approx.f16x2 %0, %1;" : "=r"(r) : "r"(x));
    return r;
}
// D = A(16x16 f16) * B(16x8 f16) + C (f32 accum)
__device__ __forceinline__ void mma16816(float& d0, float& d1, float& d2, float& d3,
                                         uint a0, uint a1, uint a2, uint a3,
                                         uint b0, uint b1,
                                         float c0, float c1, float c2, float c3) {
    asm("mma.sync.aligned.m16n8k16.row.col.f32.f16.f16.f32 "
        "{%0,%1,%2,%3}, {%4,%5,%6,%7}, {%8,%9}, {%10,%11,%12,%13};"
        : "=f"(d0), "=f"(d1), "=f"(d2), "=f"(d3)
        : "r"(a0), "r"(a1), "r"(a2), "r"(a3), "r"(b0), "r"(b1),
          "f"(c0), "f"(c1), "f"(c2), "f"(c3));
}
// D(f16x2 x2) = A(16x16 f16) * B(16x8 f16) + 0   — f16 accumulate output.
// D regs come back as the exact f16x2 pairs ex2.f16x2 consumes.
__device__ __forceinline__ void mma16816_h(uint& d0, uint& d1,
                                           uint a0, uint a1, uint a2, uint a3,
                                           uint b0, uint b1) {
    asm("mma.sync.aligned.m16n8k16.row.col.f16.f16.f16.f16 "
        "{%0,%1}, {%2,%3,%4,%5}, {%6,%7}, {%8,%9};"
        : "=r"(d0), "=r"(d1)
        : "r"(a0), "r"(a1), "r"(a2), "r"(a3), "r"(b0), "r"(b1),
          "r"(0u), "r"(0u));
}

// ---------------------------------------------------------------------------
// Kernel 1a: GroupNorm partial sums.  512 CTAs (8 per (n,group)).
// ---------------------------------------------------------------------------
__global__ void gn_part_kernel(const float* __restrict__ x,
                               float* __restrict__ part)
{
    const int blk = blockIdx.x;             // (n*8+g)*8 + p
    const int p = blk & 7;
    const size_t base = (size_t)(blk >> 3) * (CG * HW) + (size_t)p * (CG * HW / 8);
    const float4* xp = (const float4*)(x + base);

    float s = 0.f, ss = 0.f;
    #pragma unroll 4
    for (int i = threadIdx.x; i < (CG * HW / 8) / 4; i += 256) {
        float4 v = xp[i];
        s  += v.x + v.y + v.z + v.w;
        ss += v.x * v.x + v.y * v.y + v.z * v.z + v.w * v.w;
    }
    for (int o = 16; o > 0; o >>= 1) {
        s  += __shfl_xor_sync(0xffffffffu, s, o);
        ss += __shfl_xor_sync(0xffffffffu, ss, o);
    }
    __shared__ float rs[8], rss[8];
    const int warp = threadIdx.x >> 5, lane = threadIdx.x & 31;
    if (lane == 0) { rs[warp] = s; rss[warp] = ss; }
    __syncthreads();
    if (threadIdx.x == 0) {
        float ts = 0.f, tss = 0.f;
        #pragma unroll
        for (int i = 0; i < 8; i++) { ts += rs[i]; tss += rss[i]; }
        part[blk * 2]     = ts;
        part[blk * 2 + 1] = tss;
    }
}

// ---------------------------------------------------------------------------
// Kernel 1b: GroupNorm finalize -> per-(n,c) affine.  NB CTAs x 256 thr.
// ---------------------------------------------------------------------------
__global__ void gn_final_kernel(const float* __restrict__ part,
                                const float* __restrict__ w,
                                const float* __restrict__ b,
                                float* __restrict__ A,
                                float* __restrict__ B)
{
    const int n = blockIdx.x;
    const int c = threadIdx.x;
    const int g = c >> 5;
    float s = 0.f, ss = 0.f;
    #pragma unroll
    for (int i = 0; i < 8; i++) {
        s  += part[((n * NG + g) * 8 + i) * 2];
        ss += part[((n * NG + g) * 8 + i) * 2 + 1];
    }
    const float inv_n = 1.0f / (CG * HW);
    const float mu = s * inv_n;
    const float var = ss * inv_n - mu * mu;
    const float rstd = rsqrtf(var + GN_EPS);
    const float a = w[c] * rstd;
    A[n * C + c] = a;
    B[n * C + c] = fmaf(-mu, a, b[c]);
}

// ---------------------------------------------------------------------------
// Kernel 2/4: batched GEMM — fp16 mma, 64(o) x 128(t) x 16(k), 3 CTAs/SM.
// (validated R10 structure, unchanged)
// ---------------------------------------------------------------------------
template <bool FUSE_GN, bool RESID, bool X_HALF, bool OUT_HALF>
__global__ void __launch_bounds__(256, 3)
gemm_h_kernel(const float* __restrict__ W,
              const void* __restrict__ Xv,
              const float* __restrict__ bias,
              const float* __restrict__ resid,
              const float* __restrict__ Ac,
              const float* __restrict__ Bc,
              void* __restrict__ Outv,
              int M)
{
    const int n  = blockIdx.x;
    const int o0 = blockIdx.y * 64;
    const int t0 = blockIdx.z * 128;

    __shared__ uint Wt[2][64][8];
    __shared__ uint Xt[2][8][128];
    __shared__ float sA[FUSE_GN ? C : 1];
    __shared__ float sB[FUSE_GN ? C : 1];

    const int tid  = threadIdx.x;
    const int warp = tid >> 5, lane = tid & 31;
    const int g  = lane >> 2, tq = lane & 3;
    const int wm = (warp & 1) << 5;
    const int wn = (warp >> 1) << 5;

    if (FUSE_GN) {
        if (tid < C) {
            sA[tid] = Ac[n * C + tid];
            sB[tid] = Bc[n * C + tid];
        }
        __syncthreads();
    }

    const int row_w = tid >> 2;
    const int cb    = (tid & 3) << 2;
    const int cp_x  = tid >> 5;
    const int tb    = lane << 2;

    const float* Wp = W + (size_t)(o0 + row_w) * C + cb;

    const float*  Xf0 = X_HALF ? nullptr
                    : (const float*)Xv + ((size_t)n * C + 2 * cp_x) * HW + t0 + tb;
    const float*  Xf1 = X_HALF ? nullptr : Xf0 + HW;
    const __half* Xh0 = X_HALF
                    ? (const __half*)Xv + ((size_t)n * C + 2 * cp_x) * HW + t0 + tb
                    : nullptr;
    const __half* Xh1 = X_HALF ? Xh0 + HW : nullptr;

    float4 w0 = *(const float4*)Wp;
    float4 x0, x1;
    uint2  ha, hb;
    if (X_HALF) { ha = *(const uint2*)Xh0; hb = *(const uint2*)Xh1; }
    else        { x0 = *(const float4*)Xf0; x1 = *(const float4*)Xf1; }

    float acc[2][4][4];
    #pragma unroll
    for (int i = 0; i < 2; i++)
        #pragma unroll
        for (int j = 0; j < 4; j++)
            #pragma unroll
            for (int r = 0; r < 4; r++) acc[i][j][r] = 0.f;

    const int swr = ((row_w >> 2) & 1) << 2;
    const int cp0 = cb >> 1;
    const int swa = ((g >> 2) & 1) << 2;
    const int xsw = (cp_x & 3) << 3;

    int buf = 0;
    for (int k0 = 0; k0 < C; k0 += 16) {
        {
            uint2 wlo = make_uint2(cvt_f16x2(w0.x, w0.y), cvt_f16x2(w0.z, w0.w));
            *(uint2*)&Wt[buf][row_w][cp0 ^ swr] = wlo;
            uint4 xu;
            if (X_HALF) {
                xu.x = __byte_perm(ha.x, hb.x, 0x5410);
                xu.y = __byte_perm(ha.x, hb.x, 0x7632);
                xu.z = __byte_perm(ha.y, hb.y, 0x5410);
                xu.w = __byte_perm(ha.y, hb.y, 0x7632);
            } else {
                if (FUSE_GN) {
                    const float aa0 = sA[k0 + 2 * cp_x],     bb0 = sB[k0 + 2 * cp_x];
                    const float aa1 = sA[k0 + 2 * cp_x + 1], bb1 = sB[k0 + 2 * cp_x + 1];
                    x0.x = fmaf(x0.x, aa0, bb0); x0.y = fmaf(x0.y, aa0, bb0);
                    x0.z = fmaf(x0.z, aa0, bb0); x0.w = fmaf(x0.w, aa0, bb0);
                    x1.x = fmaf(x1.x, aa1, bb1); x1.y = fmaf(x1.y, aa1, bb1);
                    x1.z = fmaf(x1.z, aa1, bb1); x1.w = fmaf(x1.w, aa1, bb1);
                }
                xu.x = cvt_f16x2(x0.x, x1.x);
                xu.y = cvt_f16x2(x0.y, x1.y);
                xu.z = cvt_f16x2(x0.z, x1.z);
                xu.w = cvt_f16x2(x0.w, x1.w);
            }
            *(uint4*)&Xt[buf][cp_x][tb ^ xsw] = xu;
        }
        if (k0 + 16 < C) {
            w0 = *(const float4*)(Wp + k0 + 16);
            if (X_HALF) {
                ha = *(const uint2*)(Xh0 + (size_t)(k0 + 16) * HW);
                hb = *(const uint2*)(Xh1 + (size_t)(k0 + 16) * HW);
            } else {
                x0 = *(const float4*)(Xf0 + (size_t)(k0 + 16) * HW);
                x1 = *(const float4*)(Xf1 + (size_t)(k0 + 16) * HW);
            }
        }
        __syncthreads();

        uint A[2][4];
        #pragma unroll
        for (int i = 0; i < 2; i++) {
            const uint* wr0 = Wt[buf][wm + i * 16 + g];
            const uint* wr1 = Wt[buf][wm + i * 16 + 8 + g];
            A[i][0] = wr0[tq ^ swa];
            A[i][1] = wr1[tq ^ swa];
            A[i][2] = wr0[(4 + tq) ^ swa];
            A[i][3] = wr1[(4 + tq) ^ swa];
        }
        uint Bf[4][2];
        #pragma unroll
        for (int j = 0; j < 4; j++) {
            const int col = (wn + j * 8 + g) ^ (tq << 3);
            Bf[j][0] = Xt[buf][tq][col];
            Bf[j][1] = Xt[buf][4 + tq][col];
        }
        #pragma unroll
        for (int i = 0; i < 2; i++)
            #pragma unroll
            for (int j = 0; j < 4; j++)
                mma16816(acc[i][j][0], acc[i][j][1], acc[i][j][2], acc[i][j][3],
                         A[i][0], A[i][1], A[i][2], A[i][3],
                         Bf[j][0], Bf[j][1],
                         acc[i][j][0], acc[i][j][1], acc[i][j][2], acc[i][j][3]);
        buf ^= 1;
    }

    #pragma unroll
    for (int i = 0; i < 2; i++) {
        const int r0 = o0 + wm + i * 16 + g;
        const int r1 = r0 + 8;
        const float bv0 = bias[r0];
        const float bv1 = bias[r1];
        #pragma unroll
        for (int j = 0; j < 4; j++) {
            const int col = t0 + wn + j * 8 + 2 * tq;
            const size_t idx0 = ((size_t)n * M + r0) * HW + col;
            const size_t idx1 = ((size_t)n * M + r1) * HW + col;
            float2 v0 = make_float2(acc[i][j][0] + bv0, acc[i][j][1] + bv0);
            float2 v1 = make_float2(acc[i][j][2] + bv1, acc[i][j][3] + bv1);
            if (OUT_HALF) {
                __half* Oh = (__half*)Outv;
                *(__half2*)(Oh + idx0) = __floats2half2_rn(v0.x, v0.y);
                *(__half2*)(Oh + idx1) = __floats2half2_rn(v1.x, v1.y);
            } else {
                float* Of = (float*)Outv;
                if (RESID) {
                    const float2 r0v = *(const float2*)(resid + idx0);
                    const float2 r1v = *(const float2*)(resid + idx1);
                    v0.x += r0v.x; v0.y += r0v.y;
                    v1.x += r1v.x; v1.y += r1v.y;
                }
                *(float2*)(Of + idx0) = v0;
                *(float2*)(Of + idx1) = v1;
            }
        }
    }
}

// ---------------------------------------------------------------------------
// Kernel 3: fused attention — fp16 tensor cores.
// QK scores via f16-accumulate MMA: D regs are the f16x2 pairs that feed
// ex2.f16x2 directly — no cvt in the hot loop.  Denominator via ones-column
// MMA (f32).  8 core issues per 16x16 strip.
// ---------------------------------------------------------------------------
__global__ void __launch_bounds__(256, 2)
attn_kernel(const __half* __restrict__ qkv, __half* __restrict__ y)
{
    __shared__ uint Kh[4096];   // [j][key^(j<<3)]  j = d-pair
    __shared__ uint Vs[4096];   // [d][kp^(d<<2)]   kp = key-pair

    const int b = blockIdx.x;        // n*32 + h
    const int h = b & 31;
    const int n = b >> 5;
    const int tid = threadIdx.x;
    const int warp = tid >> 5, lane = tid & 31;
    const int g = lane >> 2, t = lane & 3;

    const __half* qbase = qkv + ((size_t)n * 3 * C + h * HD) * HW;
    const __half* kbase = qbase + (size_t)C * HW;
    const __half* vbase = qbase + (size_t)2 * C * HW;

    for (int idx = tid; idx < 4096; idx += 256) {
        const int j = idx >> 10, key = idx & 1023;
        __half2 hh = __halves2half2(kbase[(2 * j) * HW + key],
                                    kbase[(2 * j + 1) * HW + key]);
        Kh[(j << 10) | (key ^ (j << 3))] = *(uint*)&hh;
    }
    for (int idx = tid; idx < 4096; idx += 256) {
        const int d = idx >> 9, kp = idx & 511;
        Vs[(d << 9) | (kp ^ (d << 2))] =
            ((const uint*)(vbase + (size_t)d * HW))[kp];
    }
    __syncthreads();

    const float qscale = 0.35355339059327373f * 1.4426950408889634f;

    uint qa0[8], qa1[8];
    #pragma unroll
    for (int s = 0; s < 8; s++) {
        const int q0 = (warp + 8 * s) << 4;
        const __half* qd0 = qbase + (2 * t) * HW;
        const __half* qd1 = qbase + (2 * t + 1) * HW;
        qa0[s] = cvt_f16x2(__half2float(qd0[q0 + g]) * qscale,
                           __half2float(qd1[q0 + g]) * qscale);
        qa1[s] = cvt_f16x2(__half2float(qd0[q0 + 8 + g]) * qscale,
                           __half2float(qd1[q0 + 8 + g]) * qscale);
    }

    float pv[8][4];
    float ls[8][4];   // ones-column mma accumulators (col0 = row sums)
    #pragma unroll
    for (int s = 0; s < 8; s++) {
        pv[s][0] = pv[s][1] = pv[s][2] = pv[s][3] = 0.f;
        ls[s][0] = ls[s][1] = ls[s][2] = ls[s][3] = 0.f;
    }

    const uint zero = 0u;
    // B-fragment of ones in column 0 only: col = lane>>2, so lanes g==0.
    const uint ones = (g == 0) ? 0x3C003C00u : 0u;

    #pragma unroll 1
    for (int kb = 0; kb < 64; kb++) {
        const int key0 = kb << 4;
        const uint kf0 = Kh[(t << 10) | ((key0 + g) ^ (t << 3))];
        const uint kf1 = Kh[(t << 10) | ((key0 + 8 + g) ^ (t << 3))];
        const int kp0 = kb << 3;
        const uint vf0 = Vs[(g << 9) | ((kp0 + t) ^ (g << 2))];
        const uint vf1 = Vs[(g << 9) | ((kp0 + 4 + t) ^ (g << 2))];

        #pragma unroll
        for (int s = 0; s < 8; s++) {
            uint e0, e1, f0, f1;
            // scores, keys 0-7 and 8-15 (f16 accumulate -> f16x2 D regs)
            mma16816_h(e0, e1, qa0[s], qa1[s], zero, zero, kf0, zero);
            mma16816_h(f0, f1, qa0[s], qa1[s], zero, zero, kf1, zero);
            const uint pa0 = ex2_f16x2(e0);
            const uint pa1 = ex2_f16x2(e1);
            const uint pa2 = ex2_f16x2(f0);
            const uint pa3 = ex2_f16x2(f1);
            // row sums via tensor pipe (col0 of D)
            mma16816(ls[s][0], ls[s][1], ls[s][2], ls[s][3],
                     pa0, pa1, pa2, pa3, ones, ones,
                     ls[s][0], ls[s][1], ls[s][2], ls[s][3]);
            // PV += P * V
            mma16816(pv[s][0], pv[s][1], pv[s][2], pv[s][3],
                     pa0, pa1, pa2, pa3, vf0, vf1,
                     pv[s][0], pv[s][1], pv[s][2], pv[s][3]);
        }
    }

    __half* yb = y + ((size_t)n * C + h * HD) * HW;
    #pragma unroll
    for (int s = 0; s < 8; s++) {
        // row sums live on lanes tq==0 (col 0); broadcast within each row group
        const float la = __shfl_sync(0xffffffffu, ls[s][0], lane & 28);
        const float lb = __shfl_sync(0xffffffffu, ls[s][2], lane & 28);
        const float inva = __fdividef(1.0f, la);
        const float invb = __fdividef(1.0f, lb);
        const int q0 = (warp + 8 * s) << 4;
        yb[(2 * t) * HW + q0 + g]         = __float2half(pv[s][0] * inva);
        yb[(2 * t + 1) * HW + q0 + g]     = __float2half(pv[s][1] * inva);
        yb[(2 * t) * HW + q0 + 8 + g]     = __float2half(pv[s][2] * invb);
        yb[(2 * t + 1) * HW + q0 + 8 + g] = __float2half(pv[s][3] * invb);
    }
}

// ---------------------------------------------------------------------------
extern "C" void kernel_launch(void* const* d_in, const int* in_sizes, int n_in,
                              void* d_out, int out_size)
{
    const float* x     = (const float*)d_in[0];
    const float* gn_w  = (const float*)d_in[1];
    const float* gn_b  = (const float*)d_in[2];
    const float* qkv_w = (const float*)d_in[3];
    const float* qkv_b = (const float*)d_in[4];
    const float* out_w = (const float*)d_in[5];
    const float* out_b = (const float*)d_in[6];
    float* out = (float*)d_out;

    __half *qkvh, *yh;
    float *A, *B, *part;
    cudaGetSymbolAddress((void**)&qkvh, g_qkvh);
    cudaGetSymbolAddress((void**)&yh,   g_yh);
    cudaGetSymbolAddress((void**)&A,    g_A);
    cudaGetSymbolAddress((void**)&B,    g_B);
    cudaGetSymbolAddress((void**)&part, g_part);

    // 1. GroupNorm stats: full-chip partial reduce + tiny finalize
    gn_part_kernel<<<NB * NG * 8, 256>>>(x, part);
    gn_final_kernel<<<NB, 256>>>(part, gn_w, gn_b, A, B);

    // 2. QKV projection (fp16 mma) with fused GN; fp16 output
    {
        dim3 grid(NB, (3 * C) / 64, HW / 128);
        gemm_h_kernel<true, false, false, true><<<grid, 256>>>(
            qkv_w, x, qkv_b, nullptr, A, B, qkvh, 3 * C);
    }

    // 3. Attention: 256 CTAs (1 per (n,h)), fp16 in/out
    attn_kernel<<<NB * NH, 256>>>(qkvh, yh);

    // 4. Output projection (fp16 mma, half X) + bias + residual, fp32 out
    {
        dim3 grid(NB, C / 64, HW / 128);
        gemm_h_kernel<false, true, true, false><<<grid, 256>>>(
            out_w, yh, out_b, x, nullptr, nullptr, out, C);
    }
}

// round 14
// speedup vs baseline: 1.3527x; 1.3527x over previous
#include <cuda_runtime.h>
#include <cuda_bf16.h>
#include <cuda_fp16.h>
#include <math.h>

// Problem constants
#define NB 8        // batch
#define C 256       // channels
#define HW 1024     // 32*32
#define NH 32       // heads
#define HD 8        // head dim
#define NG 8        // groupnorm groups
#define CG 32       // channels per group
#define GN_EPS 1e-5f

// Scratch (allocation-free rule: __device__ globals)
__device__ __half g_qkvh[(size_t)NB * 3 * C * HW]; // 12 MB (fp16 qkv)
__device__ __half g_yh[(size_t)NB * C * HW];       // 4 MB (fp16 y)
__device__ float  g_A[NB * C];                     // per-(n,c) GN scale
__device__ float  g_B[NB * C];                     // per-(n,c) GN shift
__device__ float  g_part[NB * NG * 8 * 2];         // GN partial sums

typedef unsigned int uint;

// ---------------------------------------------------------------------------
// fp16 / mma helpers
// ---------------------------------------------------------------------------
__device__ __forceinline__ uint cvt_f16x2(float lo, float hi) {
    uint r;
    asm("cvt.rn.f16x2.f32 %0, %1, %2;" : "=r"(r) : "f"(hi), "f"(lo));
    return r;
}
__device__ __forceinline__ uint ex2_f16x2(uint x) {
    uint r;
    asm("ex2.approx.f16x2 %0, %1;" : "=r"(r) : "r"(x));
    return r;
}
// D = A(16x16 f16) * B(16x8 f16) + C (f32 accum)
__device__ __forceinline__ void mma16816(float& d0, float& d1, float& d2, float& d3,
                                         uint a0, uint a1, uint a2, uint a3,
                                         uint b0, uint b1,
                                         float c0, float c1, float c2, float c3) {
    asm("mma.sync.aligned.m16n8k16.row.col.f32.f16.f16.f32 "
        "{%0,%1,%2,%3}, {%4,%5,%6,%7}, {%8,%9}, {%10,%11,%12,%13};"
        : "=f"(d0), "=f"(d1), "=f"(d2), "=f"(d3)
        : "r"(a0), "r"(a1), "r"(a2), "r"(a3), "r"(b0), "r"(b1),
          "f"(c0), "f"(c1), "f"(c2), "f"(c3));
}

// ---------------------------------------------------------------------------
// Kernel 1a: GroupNorm partial sums.  512 CTAs (8 per (n,group)).
// ---------------------------------------------------------------------------
__global__ void gn_part_kernel(const float* __restrict__ x,
                               float* __restrict__ part)
{
    const int blk = blockIdx.x;             // (n*8+g)*8 + p
    const int p = blk & 7;
    const size_t base = (size_t)(blk >> 3) * (CG * HW) + (size_t)p * (CG * HW / 8);
    const float4* xp = (const float4*)(x + base);

    float s = 0.f, ss = 0.f;
    #pragma unroll 4
    for (int i = threadIdx.x; i < (CG * HW / 8) / 4; i += 256) {
        float4 v = xp[i];
        s  += v.x + v.y + v.z + v.w;
        ss += v.x * v.x + v.y * v.y + v.z * v.z + v.w * v.w;
    }
    for (int o = 16; o > 0; o >>= 1) {
        s  += __shfl_xor_sync(0xffffffffu, s, o);
        ss += __shfl_xor_sync(0xffffffffu, ss, o);
    }
    __shared__ float rs[8], rss[8];
    const int warp = threadIdx.x >> 5, lane = threadIdx.x & 31;
    if (lane == 0) { rs[warp] = s; rss[warp] = ss; }
    __syncthreads();
    if (threadIdx.x == 0) {
        float ts = 0.f, tss = 0.f;
        #pragma unroll
        for (int i = 0; i < 8; i++) { ts += rs[i]; tss += rss[i]; }
        part[blk * 2]     = ts;
        part[blk * 2 + 1] = tss;
    }
}

// ---------------------------------------------------------------------------
// Kernel 1b: GroupNorm finalize -> per-(n,c) affine.  NB CTAs x 256 thr.
// ---------------------------------------------------------------------------
__global__ void gn_final_kernel(const float* __restrict__ part,
                                const float* __restrict__ w,
                                const float* __restrict__ b,
                                float* __restrict__ A,
                                float* __restrict__ B)
{
    const int n = blockIdx.x;
    const int c = threadIdx.x;
    const int g = c >> 5;
    float s = 0.f, ss = 0.f;
    #pragma unroll
    for (int i = 0; i < 8; i++) {
        s  += part[((n * NG + g) * 8 + i) * 2];
        ss += part[((n * NG + g) * 8 + i) * 2 + 1];
    }
    const float inv_n = 1.0f / (CG * HW);
    const float mu = s * inv_n;
    const float var = ss * inv_n - mu * mu;
    const float rstd = rsqrtf(var + GN_EPS);
    const float a = w[c] * rstd;
    A[n * C + c] = a;
    B[n * C + c] = fmaf(-mu, a, b[c]);
}

// ---------------------------------------------------------------------------
// Kernel 2/4: batched GEMM — fp16 mma, 64(o) x 128(t) x 16(k), 3 CTAs/SM.
// (validated R10 structure, unchanged)
// ---------------------------------------------------------------------------
template <bool FUSE_GN, bool RESID, bool X_HALF, bool OUT_HALF>
__global__ void __launch_bounds__(256, 3)
gemm_h_kernel(const float* __restrict__ W,
              const void* __restrict__ Xv,
              const float* __restrict__ bias,
              const float* __restrict__ resid,
              const float* __restrict__ Ac,
              const float* __restrict__ Bc,
              void* __restrict__ Outv,
              int M)
{
    const int n  = blockIdx.x;
    const int o0 = blockIdx.y * 64;
    const int t0 = blockIdx.z * 128;

    __shared__ uint Wt[2][64][8];
    __shared__ uint Xt[2][8][128];
    __shared__ float sA[FUSE_GN ? C : 1];
    __shared__ float sB[FUSE_GN ? C : 1];

    const int tid  = threadIdx.x;
    const int warp = tid >> 5, lane = tid & 31;
    const int g  = lane >> 2, tq = lane & 3;
    const int wm = (warp & 1) << 5;
    const int wn = (warp >> 1) << 5;

    if (FUSE_GN) {
        if (tid < C) {
            sA[tid] = Ac[n * C + tid];
            sB[tid] = Bc[n * C + tid];
        }
        __syncthreads();
    }

    const int row_w = tid >> 2;
    const int cb    = (tid & 3) << 2;
    const int cp_x  = tid >> 5;
    const int tb    = lane << 2;

    const float* Wp = W + (size_t)(o0 + row_w) * C + cb;

    const float*  Xf0 = X_HALF ? nullptr
                    : (const float*)Xv + ((size_t)n * C + 2 * cp_x) * HW + t0 + tb;
    const float*  Xf1 = X_HALF ? nullptr : Xf0 + HW;
    const __half* Xh0 = X_HALF
                    ? (const __half*)Xv + ((size_t)n * C + 2 * cp_x) * HW + t0 + tb
                    : nullptr;
    const __half* Xh1 = X_HALF ? Xh0 + HW : nullptr;

    float4 w0 = *(const float4*)Wp;
    float4 x0, x1;
    uint2  ha, hb;
    if (X_HALF) { ha = *(const uint2*)Xh0; hb = *(const uint2*)Xh1; }
    else        { x0 = *(const float4*)Xf0; x1 = *(const float4*)Xf1; }

    float acc[2][4][4];
    #pragma unroll
    for (int i = 0; i < 2; i++)
        #pragma unroll
        for (int j = 0; j < 4; j++)
            #pragma unroll
            for (int r = 0; r < 4; r++) acc[i][j][r] = 0.f;

    const int swr = ((row_w >> 2) & 1) << 2;
    const int cp0 = cb >> 1;
    const int swa = ((g >> 2) & 1) << 2;
    const int xsw = (cp_x & 3) << 3;

    int buf = 0;
    for (int k0 = 0; k0 < C; k0 += 16) {
        {
            uint2 wlo = make_uint2(cvt_f16x2(w0.x, w0.y), cvt_f16x2(w0.z, w0.w));
            *(uint2*)&Wt[buf][row_w][cp0 ^ swr] = wlo;
            uint4 xu;
            if (X_HALF) {
                xu.x = __byte_perm(ha.x, hb.x, 0x5410);
                xu.y = __byte_perm(ha.x, hb.x, 0x7632);
                xu.z = __byte_perm(ha.y, hb.y, 0x5410);
                xu.w = __byte_perm(ha.y, hb.y, 0x7632);
            } else {
                if (FUSE_GN) {
                    const float aa0 = sA[k0 + 2 * cp_x],     bb0 = sB[k0 + 2 * cp_x];
                    const float aa1 = sA[k0 + 2 * cp_x + 1], bb1 = sB[k0 + 2 * cp_x + 1];
                    x0.x = fmaf(x0.x, aa0, bb0); x0.y = fmaf(x0.y, aa0, bb0);
                    x0.z = fmaf(x0.z, aa0, bb0); x0.w = fmaf(x0.w, aa0, bb0);
                    x1.x = fmaf(x1.x, aa1, bb1); x1.y = fmaf(x1.y, aa1, bb1);
                    x1.z = fmaf(x1.z, aa1, bb1); x1.w = fmaf(x1.w, aa1, bb1);
                }
                xu.x = cvt_f16x2(x0.x, x1.x);
                xu.y = cvt_f16x2(x0.y, x1.y);
                xu.z = cvt_f16x2(x0.z, x1.z);
                xu.w = cvt_f16x2(x0.w, x1.w);
            }
            *(uint4*)&Xt[buf][cp_x][tb ^ xsw] = xu;
        }
        if (k0 + 16 < C) {
            w0 = *(const float4*)(Wp + k0 + 16);
            if (X_HALF) {
                ha = *(const uint2*)(Xh0 + (size_t)(k0 + 16) * HW);
                hb = *(const uint2*)(Xh1 + (size_t)(k0 + 16) * HW);
            } else {
                x0 = *(const float4*)(Xf0 + (size_t)(k0 + 16) * HW);
                x1 = *(const float4*)(Xf1 + (size_t)(k0 + 16) * HW);
            }
        }
        __syncthreads();

        uint A[2][4];
        #pragma unroll
        for (int i = 0; i < 2; i++) {
            const uint* wr0 = Wt[buf][wm + i * 16 + g];
            const uint* wr1 = Wt[buf][wm + i * 16 + 8 + g];
            A[i][0] = wr0[tq ^ swa];
            A[i][1] = wr1[tq ^ swa];
            A[i][2] = wr0[(4 + tq) ^ swa];
            A[i][3] = wr1[(4 + tq) ^ swa];
        }
        uint Bf[4][2];
        #pragma unroll
        for (int j = 0; j < 4; j++) {
            const int col = (wn + j * 8 + g) ^ (tq << 3);
            Bf[j][0] = Xt[buf][tq][col];
            Bf[j][1] = Xt[buf][4 + tq][col];
        }
        #pragma unroll
        for (int i = 0; i < 2; i++)
            #pragma unroll
            for (int j = 0; j < 4; j++)
                mma16816(acc[i][j][0], acc[i][j][1], acc[i][j][2], acc[i][j][3],
                         A[i][0], A[i][1], A[i][2], A[i][3],
                         Bf[j][0], Bf[j][1],
                         acc[i][j][0], acc[i][j][1], acc[i][j][2], acc[i][j][3]);
        buf ^= 1;
    }

    #pragma unroll
    for (int i = 0; i < 2; i++) {
        const int r0 = o0 + wm + i * 16 + g;
        const int r1 = r0 + 8;
        const float bv0 = bias[r0];
        const float bv1 = bias[r1];
        #pragma unroll
        for (int j = 0; j < 4; j++) {
            const int col = t0 + wn + j * 8 + 2 * tq;
            const size_t idx0 = ((size_t)n * M + r0) * HW + col;
            const size_t idx1 = ((size_t)n * M + r1) * HW + col;
            float2 v0 = make_float2(acc[i][j][0] + bv0, acc[i][j][1] + bv0);
            float2 v1 = make_float2(acc[i][j][2] + bv1, acc[i][j][3] + bv1);
            if (OUT_HALF) {
                __half* Oh = (__half*)Outv;
                *(__half2*)(Oh + idx0) = __floats2half2_rn(v0.x, v0.y);
                *(__half2*)(Oh + idx1) = __floats2half2_rn(v1.x, v1.y);
            } else {
                float* Of = (float*)Outv;
                if (RESID) {
                    const float2 r0v = *(const float2*)(resid + idx0);
                    const float2 r1v = *(const float2*)(resid + idx1);
                    v0.x += r0v.x; v0.y += r0v.y;
                    v1.x += r1v.x; v1.y += r1v.y;
                }
                *(float2*)(Of + idx0) = v0;
                *(float2*)(Of + idx1) = v1;
            }
        }
    }
}

// ---------------------------------------------------------------------------
// Kernel 3: fused attention — fp16 tensor cores, f32-accum MMAs (R11 loop,
// the validated fast variant).  NOW: 512 CTAs (2 per head, half queries
// each), 4 strips/warp, 3 CTAs/SM for latency hiding.
// ---------------------------------------------------------------------------
__global__ void __launch_bounds__(256, 3)
attn_kernel(const __half* __restrict__ qkv, __half* __restrict__ y)
{
    __shared__ uint Kh[4096];   // [j][key^(j<<3)]  j = d-pair
    __shared__ uint Vs[4096];   // [d][kp^(d<<2)]   kp = key-pair

    const int b  = blockIdx.x;       // (n*32 + h)*2 + qh
    const int qh = b & 1;
    const int h  = (b >> 1) & 31;
    const int n  = b >> 6;
    const int tid = threadIdx.x;
    const int warp = tid >> 5, lane = tid & 31;
    const int g = lane >> 2, t = lane & 3;

    const __half* qbase = qkv + ((size_t)n * 3 * C + h * HD) * HW;
    const __half* kbase = qbase + (size_t)C * HW;
    const __half* vbase = qbase + (size_t)2 * C * HW;

    for (int idx = tid; idx < 4096; idx += 256) {
        const int j = idx >> 10, key = idx & 1023;
        __half2 hh = __halves2half2(kbase[(2 * j) * HW + key],
                                    kbase[(2 * j + 1) * HW + key]);
        Kh[(j << 10) | (key ^ (j << 3))] = *(uint*)&hh;
    }
    for (int idx = tid; idx < 4096; idx += 256) {
        const int d = idx >> 9, kp = idx & 511;
        Vs[(d << 9) | (kp ^ (d << 2))] =
            ((const uint*)(vbase + (size_t)d * HW))[kp];
    }
    __syncthreads();

    const float qscale = 0.35355339059327373f * 1.4426950408889634f;

    uint qa0[4], qa1[4];
    #pragma unroll
    for (int s = 0; s < 4; s++) {
        const int q0 = (qh << 9) + ((warp + 8 * s) << 4);
        const __half* qd0 = qbase + (2 * t) * HW;
        const __half* qd1 = qbase + (2 * t + 1) * HW;
        qa0[s] = cvt_f16x2(__half2float(qd0[q0 + g]) * qscale,
                           __half2float(qd1[q0 + g]) * qscale);
        qa1[s] = cvt_f16x2(__half2float(qd0[q0 + 8 + g]) * qscale,
                           __half2float(qd1[q0 + 8 + g]) * qscale);
    }

    float pv[4][4];
    float ls[4][4];   // ones-column mma accumulators (col0 = row sums)
    #pragma unroll
    for (int s = 0; s < 4; s++) {
        pv[s][0] = pv[s][1] = pv[s][2] = pv[s][3] = 0.f;
        ls[s][0] = ls[s][1] = ls[s][2] = ls[s][3] = 0.f;
    }

    const uint zero = 0u;
    // B-fragment of ones in column 0 only: col = lane>>2, so lanes g==0.
    const uint ones = (g == 0) ? 0x3C003C00u : 0u;

    #pragma unroll 1
    for (int kb = 0; kb < 64; kb++) {
        const int key0 = kb << 4;
        const uint kf0 = Kh[(t << 10) | ((key0 + g) ^ (t << 3))];
        const uint kf1 = Kh[(t << 10) | ((key0 + 8 + g) ^ (t << 3))];
        const int kp0 = kb << 3;
        const uint vf0 = Vs[(g << 9) | ((kp0 + t) ^ (g << 2))];
        const uint vf1 = Vs[(g << 9) | ((kp0 + 4 + t) ^ (g << 2))];

        #pragma unroll
        for (int s = 0; s < 4; s++) {
            float c0, c1, c2, c3, d0, d1, d2, d3;
            mma16816(c0, c1, c2, c3, qa0[s], qa1[s], zero, zero, kf0, zero,
                     0.f, 0.f, 0.f, 0.f);
            mma16816(d0, d1, d2, d3, qa0[s], qa1[s], zero, zero, kf1, zero,
                     0.f, 0.f, 0.f, 0.f);
            const uint pa0 = ex2_f16x2(cvt_f16x2(c0, c1));
            const uint pa1 = ex2_f16x2(cvt_f16x2(c2, c3));
            const uint pa2 = ex2_f16x2(cvt_f16x2(d0, d1));
            const uint pa3 = ex2_f16x2(cvt_f16x2(d2, d3));
            // row sums via tensor pipe (col0 of D)
            mma16816(ls[s][0], ls[s][1], ls[s][2], ls[s][3],
                     pa0, pa1, pa2, pa3, ones, ones,
                     ls[s][0], ls[s][1], ls[s][2], ls[s][3]);
            // PV += P * V
            mma16816(pv[s][0], pv[s][1], pv[s][2], pv[s][3],
                     pa0, pa1, pa2, pa3, vf0, vf1,
                     pv[s][0], pv[s][1], pv[s][2], pv[s][3]);
        }
    }

    __half* yb = y + ((size_t)n * C + h * HD) * HW;
    #pragma unroll
    for (int s = 0; s < 4; s++) {
        // row sums live on lanes tq==0 (col 0); broadcast within each row group
        const float la = __shfl_sync(0xffffffffu, ls[s][0], lane & 28);
        const float lb = __shfl_sync(0xffffffffu, ls[s][2], lane & 28);
        const float inva = __fdividef(1.0f, la);
        const float invb = __fdividef(1.0f, lb);
        const int q0 = (qh << 9) + ((warp + 8 * s) << 4);
        yb[(2 * t) * HW + q0 + g]         = __float2half(pv[s][0] * inva);
        yb[(2 * t + 1) * HW + q0 + g]     = __float2half(pv[s][1] * inva);
        yb[(2 * t) * HW + q0 + 8 + g]     = __float2half(pv[s][2] * invb);
        yb[(2 * t + 1) * HW + q0 + 8 + g] = __float2half(pv[s][3] * invb);
    }
}

// ---------------------------------------------------------------------------
extern "C" void kernel_launch(void* const* d_in, const int* in_sizes, int n_in,
                              void* d_out, int out_size)
{
    const float* x     = (const float*)d_in[0];
    const float* gn_w  = (const float*)d_in[1];
    const float* gn_b  = (const float*)d_in[2];
    const float* qkv_w = (const float*)d_in[3];
    const float* qkv_b = (const float*)d_in[4];
    const float* out_w = (const float*)d_in[5];
    const float* out_b = (const float*)d_in[6];
    float* out = (float*)d_out;

    __half *qkvh, *yh;
    float *A, *B, *part;
    cudaGetSymbolAddress((void**)&qkvh, g_qkvh);
    cudaGetSymbolAddress((void**)&yh,   g_yh);
    cudaGetSymbolAddress((void**)&A,    g_A);
    cudaGetSymbolAddress((void**)&B,    g_B);
    cudaGetSymbolAddress((void**)&part, g_part);

    // 1. GroupNorm stats: full-chip partial reduce + tiny finalize
    gn_part_kernel<<<NB * NG * 8, 256>>>(x, part);
    gn_final_kernel<<<NB, 256>>>(part, gn_w, gn_b, A, B);

    // 2. QKV projection (fp16 mma) with fused GN; fp16 output
    {
        dim3 grid(NB, (3 * C) / 64, HW / 128);
        gemm_h_kernel<true, false, false, true><<<grid, 256>>>(
            qkv_w, x, qkv_b, nullptr, A, B, qkvh, 3 * C);
    }

    // 3. Attention: 512 CTAs (2 per head), 3 CTAs/SM
    attn_kernel<<<NB * NH * 2, 256>>>(qkvh, yh);

    // 4. Output projection (fp16 mma, half X) + bias + residual, fp32 out
    {
        dim3 grid(NB, C / 64, HW / 128);
        gemm_h_kernel<false, true, true, false><<<grid, 256>>>(
            out_w, yh, out_b, x, nullptr, nullptr, out, C);
    }
}

// round 15
// speedup vs baseline: 1.4286x; 1.0562x over previous
#include <cuda_runtime.h>
#include <cuda_bf16.h>
#include <cuda_fp16.h>
#include <math.h>

// Problem constants
#define NB 8        // batch
#define C 256       // channels
#define HW 1024     // 32*32
#define NH 32       // heads
#define HD 8        // head dim
#define NG 8        // groupnorm groups
#define CG 32       // channels per group
#define GN_EPS 1e-5f

// Scratch (allocation-free rule: __device__ globals)
__device__ __half g_qkvh[(size_t)NB * 3 * C * HW]; // 12 MB (fp16 qkv)
__device__ __half g_yh[(size_t)NB * C * HW];       // 4 MB (fp16 y)
__device__ float  g_A[NB * C];                     // per-(n,c) GN scale
__device__ float  g_B[NB * C];                     // per-(n,c) GN shift
__device__ float  g_part[NB * NG * 8 * 2];         // GN partial sums

typedef unsigned int uint;

// ---------------------------------------------------------------------------
// fp16 / mma helpers
// ---------------------------------------------------------------------------
__device__ __forceinline__ uint cvt_f16x2(float lo, float hi) {
    uint r;
    asm("cvt.rn.f16x2.f32 %0, %1, %2;" : "=r"(r) : "f"(hi), "f"(lo));
    return r;
}
__device__ __forceinline__ uint ex2_f16x2(uint x) {
    uint r;
    asm("ex2.approx.f16x2 %0, %1;" : "=r"(r) : "r"(x));
    return r;
}
// D = A(16x16 f16) * B(16x8 f16) + C (f32 accum)
__device__ __forceinline__ void mma16816(float& d0, float& d1, float& d2, float& d3,
                                         uint a0, uint a1, uint a2, uint a3,
                                         uint b0, uint b1,
                                         float c0, float c1, float c2, float c3) {
    asm("mma.sync.aligned.m16n8k16.row.col.f32.f16.f16.f32 "
        "{%0,%1,%2,%3}, {%4,%5,%6,%7}, {%8,%9}, {%10,%11,%12,%13};"
        : "=f"(d0), "=f"(d1), "=f"(d2), "=f"(d3)
        : "r"(a0), "r"(a1), "r"(a2), "r"(a3), "r"(b0), "r"(b1),
          "f"(c0), "f"(c1), "f"(c2), "f"(c3));
}
// D = A(16x8 f16) * B(8x8 f16) + 0 — exact k=8 (head dim), no zero padding.
// A frags = same (a0,a1) lane mapping as k16 low-k half; B = single reg.
__device__ __forceinline__ void mma16808(float& d0, float& d1, float& d2, float& d3,
                                         uint a0, uint a1, uint b0) {
    asm("mma.sync.aligned.m16n8k8.row.col.f32.f16.f16.f32 "
        "{%0,%1,%2,%3}, {%4,%5}, {%6}, {%7,%8,%9,%10};"
        : "=f"(d0), "=f"(d1), "=f"(d2), "=f"(d3)
        : "r"(a0), "r"(a1), "r"(b0),
          "f"(0.f), "f"(0.f), "f"(0.f), "f"(0.f));
}

// ---------------------------------------------------------------------------
// Kernel 1a: GroupNorm partial sums.  512 CTAs (8 per (n,group)).
// ---------------------------------------------------------------------------
__global__ void gn_part_kernel(const float* __restrict__ x,
                               float* __restrict__ part)
{
    const int blk = blockIdx.x;             // (n*8+g)*8 + p
    const int p = blk & 7;
    const size_t base = (size_t)(blk >> 3) * (CG * HW) + (size_t)p * (CG * HW / 8);
    const float4* xp = (const float4*)(x + base);

    float s = 0.f, ss = 0.f;
    #pragma unroll 4
    for (int i = threadIdx.x; i < (CG * HW / 8) / 4; i += 256) {
        float4 v = xp[i];
        s  += v.x + v.y + v.z + v.w;
        ss += v.x * v.x + v.y * v.y + v.z * v.z + v.w * v.w;
    }
    for (int o = 16; o > 0; o >>= 1) {
        s  += __shfl_xor_sync(0xffffffffu, s, o);
        ss += __shfl_xor_sync(0xffffffffu, ss, o);
    }
    __shared__ float rs[8], rss[8];
    const int warp = threadIdx.x >> 5, lane = threadIdx.x & 31;
    if (lane == 0) { rs[warp] = s; rss[warp] = ss; }
    __syncthreads();
    if (threadIdx.x == 0) {
        float ts = 0.f, tss = 0.f;
        #pragma unroll
        for (int i = 0; i < 8; i++) { ts += rs[i]; tss += rss[i]; }
        part[blk * 2]     = ts;
        part[blk * 2 + 1] = tss;
    }
}

// ---------------------------------------------------------------------------
// Kernel 1b: GroupNorm finalize -> per-(n,c) affine.  NB CTAs x 256 thr.
// ---------------------------------------------------------------------------
__global__ void gn_final_kernel(const float* __restrict__ part,
                                const float* __restrict__ w,
                                const float* __restrict__ b,
                                float* __restrict__ A,
                                float* __restrict__ B)
{
    const int n = blockIdx.x;
    const int c = threadIdx.x;
    const int g = c >> 5;
    float s = 0.f, ss = 0.f;
    #pragma unroll
    for (int i = 0; i < 8; i++) {
        s  += part[((n * NG + g) * 8 + i) * 2];
        ss += part[((n * NG + g) * 8 + i) * 2 + 1];
    }
    const float inv_n = 1.0f / (CG * HW);
    const float mu = s * inv_n;
    const float var = ss * inv_n - mu * mu;
    const float rstd = rsqrtf(var + GN_EPS);
    const float a = w[c] * rstd;
    A[n * C + c] = a;
    B[n * C + c] = fmaf(-mu, a, b[c]);
}

// ---------------------------------------------------------------------------
// Kernel 2/4: batched GEMM — fp16 mma, 64(o) x 128(t) x 16(k), 3 CTAs/SM.
// (validated R10 structure, unchanged)
// ---------------------------------------------------------------------------
template <bool FUSE_GN, bool RESID, bool X_HALF, bool OUT_HALF>
__global__ void __launch_bounds__(256, 3)
gemm_h_kernel(const float* __restrict__ W,
              const void* __restrict__ Xv,
              const float* __restrict__ bias,
              const float* __restrict__ resid,
              const float* __restrict__ Ac,
              const float* __restrict__ Bc,
              void* __restrict__ Outv,
              int M)
{
    const int n  = blockIdx.x;
    const int o0 = blockIdx.y * 64;
    const int t0 = blockIdx.z * 128;

    __shared__ uint Wt[2][64][8];
    __shared__ uint Xt[2][8][128];
    __shared__ float sA[FUSE_GN ? C : 1];
    __shared__ float sB[FUSE_GN ? C : 1];

    const int tid  = threadIdx.x;
    const int warp = tid >> 5, lane = tid & 31;
    const int g  = lane >> 2, tq = lane & 3;
    const int wm = (warp & 1) << 5;
    const int wn = (warp >> 1) << 5;

    if (FUSE_GN) {
        if (tid < C) {
            sA[tid] = Ac[n * C + tid];
            sB[tid] = Bc[n * C + tid];
        }
        __syncthreads();
    }

    const int row_w = tid >> 2;
    const int cb    = (tid & 3) << 2;
    const int cp_x  = tid >> 5;
    const int tb    = lane << 2;

    const float* Wp = W + (size_t)(o0 + row_w) * C + cb;

    const float*  Xf0 = X_HALF ? nullptr
                    : (const float*)Xv + ((size_t)n * C + 2 * cp_x) * HW + t0 + tb;
    const float*  Xf1 = X_HALF ? nullptr : Xf0 + HW;
    const __half* Xh0 = X_HALF
                    ? (const __half*)Xv + ((size_t)n * C + 2 * cp_x) * HW + t0 + tb
                    : nullptr;
    const __half* Xh1 = X_HALF ? Xh0 + HW : nullptr;

    float4 w0 = *(const float4*)Wp;
    float4 x0, x1;
    uint2  ha, hb;
    if (X_HALF) { ha = *(const uint2*)Xh0; hb = *(const uint2*)Xh1; }
    else        { x0 = *(const float4*)Xf0; x1 = *(const float4*)Xf1; }

    float acc[2][4][4];
    #pragma unroll
    for (int i = 0; i < 2; i++)
        #pragma unroll
        for (int j = 0; j < 4; j++)
            #pragma unroll
            for (int r = 0; r < 4; r++) acc[i][j][r] = 0.f;

    const int swr = ((row_w >> 2) & 1) << 2;
    const int cp0 = cb >> 1;
    const int swa = ((g >> 2) & 1) << 2;
    const int xsw = (cp_x & 3) << 3;

    int buf = 0;
    for (int k0 = 0; k0 < C; k0 += 16) {
        {
            uint2 wlo = make_uint2(cvt_f16x2(w0.x, w0.y), cvt_f16x2(w0.z, w0.w));
            *(uint2*)&Wt[buf][row_w][cp0 ^ swr] = wlo;
            uint4 xu;
            if (X_HALF) {
                xu.x = __byte_perm(ha.x, hb.x, 0x5410);
                xu.y = __byte_perm(ha.x, hb.x, 0x7632);
                xu.z = __byte_perm(ha.y, hb.y, 0x5410);
                xu.w = __byte_perm(ha.y, hb.y, 0x7632);
            } else {
                if (FUSE_GN) {
                    const float aa0 = sA[k0 + 2 * cp_x],     bb0 = sB[k0 + 2 * cp_x];
                    const float aa1 = sA[k0 + 2 * cp_x + 1], bb1 = sB[k0 + 2 * cp_x + 1];
                    x0.x = fmaf(x0.x, aa0, bb0); x0.y = fmaf(x0.y, aa0, bb0);
                    x0.z = fmaf(x0.z, aa0, bb0); x0.w = fmaf(x0.w, aa0, bb0);
                    x1.x = fmaf(x1.x, aa1, bb1); x1.y = fmaf(x1.y, aa1, bb1);
                    x1.z = fmaf(x1.z, aa1, bb1); x1.w = fmaf(x1.w, aa1, bb1);
                }
                xu.x = cvt_f16x2(x0.x, x1.x);
                xu.y = cvt_f16x2(x0.y, x1.y);
                xu.z = cvt_f16x2(x0.z, x1.z);
                xu.w = cvt_f16x2(x0.w, x1.w);
            }
            *(uint4*)&Xt[buf][cp_x][tb ^ xsw] = xu;
        }
        if (k0 + 16 < C) {
            w0 = *(const float4*)(Wp + k0 + 16);
            if (X_HALF) {
                ha = *(const uint2*)(Xh0 + (size_t)(k0 + 16) * HW);
                hb = *(const uint2*)(Xh1 + (size_t)(k0 + 16) * HW);
            } else {
                x0 = *(const float4*)(Xf0 + (size_t)(k0 + 16) * HW);
                x1 = *(const float4*)(Xf1 + (size_t)(k0 + 16) * HW);
            }
        }
        __syncthreads();

        uint A[2][4];
        #pragma unroll
        for (int i = 0; i < 2; i++) {
            const uint* wr0 = Wt[buf][wm + i * 16 + g];
            const uint* wr1 = Wt[buf][wm + i * 16 + 8 + g];
            A[i][0] = wr0[tq ^ swa];
            A[i][1] = wr1[tq ^ swa];
            A[i][2] = wr0[(4 + tq) ^ swa];
            A[i][3] = wr1[(4 + tq) ^ swa];
        }
        uint Bf[4][2];
        #pragma unroll
        for (int j = 0; j < 4; j++) {
            const int col = (wn + j * 8 + g) ^ (tq << 3);
            Bf[j][0] = Xt[buf][tq][col];
            Bf[j][1] = Xt[buf][4 + tq][col];
        }
        #pragma unroll
        for (int i = 0; i < 2; i++)
            #pragma unroll
            for (int j = 0; j < 4; j++)
                mma16816(acc[i][j][0], acc[i][j][1], acc[i][j][2], acc[i][j][3],
                         A[i][0], A[i][1], A[i][2], A[i][3],
                         Bf[j][0], Bf[j][1],
                         acc[i][j][0], acc[i][j][1], acc[i][j][2], acc[i][j][3]);
        buf ^= 1;
    }

    #pragma unroll
    for (int i = 0; i < 2; i++) {
        const int r0 = o0 + wm + i * 16 + g;
        const int r1 = r0 + 8;
        const float bv0 = bias[r0];
        const float bv1 = bias[r1];
        #pragma unroll
        for (int j = 0; j < 4; j++) {
            const int col = t0 + wn + j * 8 + 2 * tq;
            const size_t idx0 = ((size_t)n * M + r0) * HW + col;
            const size_t idx1 = ((size_t)n * M + r1) * HW + col;
            float2 v0 = make_float2(acc[i][j][0] + bv0, acc[i][j][1] + bv0);
            float2 v1 = make_float2(acc[i][j][2] + bv1, acc[i][j][3] + bv1);
            if (OUT_HALF) {
                __half* Oh = (__half*)Outv;
                *(__half2*)(Oh + idx0) = __floats2half2_rn(v0.x, v0.y);
                *(__half2*)(Oh + idx1) = __floats2half2_rn(v1.x, v1.y);
            } else {
                float* Of = (float*)Outv;
                if (RESID) {
                    const float2 r0v = *(const float2*)(resid + idx0);
                    const float2 r1v = *(const float2*)(resid + idx1);
                    v0.x += r0v.x; v0.y += r0v.y;
                    v1.x += r1v.x; v1.y += r1v.y;
                }
                *(float2*)(Of + idx0) = v0;
                *(float2*)(Of + idx1) = v1;
            }
        }
    }
}

// ---------------------------------------------------------------------------
// Kernel 3: fused attention — fp16 tensor cores.  QK via m16n8k8 (exact
// head-dim k, no zero padding -> half the QK tensor work).  Denominator via
// ones-column k16 MMA.  512 CTAs (2 per head), 3 CTAs/SM.
// ---------------------------------------------------------------------------
__global__ void __launch_bounds__(256, 3)
attn_kernel(const __half* __restrict__ qkv, __half* __restrict__ y)
{
    __shared__ uint Kh[4096];   // [j][key^(j<<3)]  j = d-pair
    __shared__ uint Vs[4096];   // [d][kp^(d<<2)]   kp = key-pair

    const int b  = blockIdx.x;       // (n*32 + h)*2 + qh
    const int qh = b & 1;
    const int h  = (b >> 1) & 31;
    const int n  = b >> 6;
    const int tid = threadIdx.x;
    const int warp = tid >> 5, lane = tid & 31;
    const int g = lane >> 2, t = lane & 3;

    const __half* qbase = qkv + ((size_t)n * 3 * C + h * HD) * HW;
    const __half* kbase = qbase + (size_t)C * HW;
    const __half* vbase = qbase + (size_t)2 * C * HW;

    for (int idx = tid; idx < 4096; idx += 256) {
        const int j = idx >> 10, key = idx & 1023;
        __half2 hh = __halves2half2(kbase[(2 * j) * HW + key],
                                    kbase[(2 * j + 1) * HW + key]);
        Kh[(j << 10) | (key ^ (j << 3))] = *(uint*)&hh;
    }
    for (int idx = tid; idx < 4096; idx += 256) {
        const int d = idx >> 9, kp = idx & 511;
        Vs[(d << 9) | (kp ^ (d << 2))] =
            ((const uint*)(vbase + (size_t)d * HW))[kp];
    }
    __syncthreads();

    const float qscale = 0.35355339059327373f * 1.4426950408889634f;

    uint qa0[4], qa1[4];
    #pragma unroll
    for (int s = 0; s < 4; s++) {
        const int q0 = (qh << 9) + ((warp + 8 * s) << 4);
        const __half* qd0 = qbase + (2 * t) * HW;
        const __half* qd1 = qbase + (2 * t + 1) * HW;
        qa0[s] = cvt_f16x2(__half2float(qd0[q0 + g]) * qscale,
                           __half2float(qd1[q0 + g]) * qscale);
        qa1[s] = cvt_f16x2(__half2float(qd0[q0 + 8 + g]) * qscale,
                           __half2float(qd1[q0 + 8 + g]) * qscale);
    }

    float pv[4][4];
    float ls[4][4];   // ones-column mma accumulators (col0 = row sums)
    #pragma unroll
    for (int s = 0; s < 4; s++) {
        pv[s][0] = pv[s][1] = pv[s][2] = pv[s][3] = 0.f;
        ls[s][0] = ls[s][1] = ls[s][2] = ls[s][3] = 0.f;
    }

    // B-fragment of ones in column 0 only: col = lane>>2, so lanes g==0.
    const uint ones = (g == 0) ? 0x3C003C00u : 0u;

    #pragma unroll 1
    for (int kb = 0; kb < 64; kb++) {
        const int key0 = kb << 4;
        const uint kf0 = Kh[(t << 10) | ((key0 + g) ^ (t << 3))];
        const uint kf1 = Kh[(t << 10) | ((key0 + 8 + g) ^ (t << 3))];
        const int kp0 = kb << 3;
        const uint vf0 = Vs[(g << 9) | ((kp0 + t) ^ (g << 2))];
        const uint vf1 = Vs[(g << 9) | ((kp0 + 4 + t) ^ (g << 2))];

        #pragma unroll
        for (int s = 0; s < 4; s++) {
            float c0, c1, c2, c3, d0, d1, d2, d3;
            // scores via exact k=8 MMA (no zero-padded k half)
            mma16808(c0, c1, c2, c3, qa0[s], qa1[s], kf0);
            mma16808(d0, d1, d2, d3, qa0[s], qa1[s], kf1);
            const uint pa0 = ex2_f16x2(cvt_f16x2(c0, c1));
            const uint pa1 = ex2_f16x2(cvt_f16x2(c2, c3));
            const uint pa2 = ex2_f16x2(cvt_f16x2(d0, d1));
            const uint pa3 = ex2_f16x2(cvt_f16x2(d2, d3));
            // row sums via tensor pipe (col0 of D)
            mma16816(ls[s][0], ls[s][1], ls[s][2], ls[s][3],
                     pa0, pa1, pa2, pa3, ones, ones,
                     ls[s][0], ls[s][1], ls[s][2], ls[s][3]);
            // PV += P * V
            mma16816(pv[s][0], pv[s][1], pv[s][2], pv[s][3],
                     pa0, pa1, pa2, pa3, vf0, vf1,
                     pv[s][0], pv[s][1], pv[s][2], pv[s][3]);
        }
    }

    __half* yb = y + ((size_t)n * C + h * HD) * HW;
    #pragma unroll
    for (int s = 0; s < 4; s++) {
        // row sums live on lanes tq==0 (col 0); broadcast within each row group
        const float la = __shfl_sync(0xffffffffu, ls[s][0], lane & 28);
        const float lb = __shfl_sync(0xffffffffu, ls[s][2], lane & 28);
        const float inva = __fdividef(1.0f, la);
        const float invb = __fdividef(1.0f, lb);
        const int q0 = (qh << 9) + ((warp + 8 * s) << 4);
        yb[(2 * t) * HW + q0 + g]         = __float2half(pv[s][0] * inva);
        yb[(2 * t + 1) * HW + q0 + g]     = __float2half(pv[s][1] * inva);
        yb[(2 * t) * HW + q0 + 8 + g]     = __float2half(pv[s][2] * invb);
        yb[(2 * t + 1) * HW + q0 + 8 + g] = __float2half(pv[s][3] * invb);
    }
}

// ---------------------------------------------------------------------------
extern "C" void kernel_launch(void* const* d_in, const int* in_sizes, int n_in,
                              void* d_out, int out_size)
{
    const float* x     = (const float*)d_in[0];
    const float* gn_w  = (const float*)d_in[1];
    const float* gn_b  = (const float*)d_in[2];
    const float* qkv_w = (const float*)d_in[3];
    const float* qkv_b = (const float*)d_in[4];
    const float* out_w = (const float*)d_in[5];
    const float* out_b = (const float*)d_in[6];
    float* out = (float*)d_out;

    __half *qkvh, *yh;
    float *A, *B, *part;
    cudaGetSymbolAddress((void**)&qkvh, g_qkvh);
    cudaGetSymbolAddress((void**)&yh,   g_yh);
    cudaGetSymbolAddress((void**)&A,    g_A);
    cudaGetSymbolAddress((void**)&B,    g_B);
    cudaGetSymbolAddress((void**)&part, g_part);

    // 1. GroupNorm stats: full-chip partial reduce + tiny finalize
    gn_part_kernel<<<NB * NG * 8, 256>>>(x, part);
    gn_final_kernel<<<NB, 256>>>(part, gn_w, gn_b, A, B);

    // 2. QKV projection (fp16 mma) with fused GN; fp16 output
    {
        dim3 grid(NB, (3 * C) / 64, HW / 128);
        gemm_h_kernel<true, false, false, true><<<grid, 256>>>(
            qkv_w, x, qkv_b, nullptr, A, B, qkvh, 3 * C);
    }

    // 3. Attention: 512 CTAs (2 per head), 3 CTAs/SM
    attn_kernel<<<NB * NH * 2, 256>>>(qkvh, yh);

    // 4. Output projection (fp16 mma, half X) + bias + residual, fp32 out
    {
        dim3 grid(NB, C / 64, HW / 128);
        gemm_h_kernel<false, true, true, false><<<grid, 256>>>(
            out_w, yh, out_b, x, nullptr, nullptr, out, C);
    }
}

// round 16
// speedup vs baseline: 1.4582x; 1.0207x over previous
#include <cuda_runtime.h>
#include <cuda_bf16.h>
#include <cuda_fp16.h>
#include <math.h>

// Problem constants
#define NB 8        // batch
#define C 256       // channels
#define HW 1024     // 32*32
#define NH 32       // heads
#define HD 8        // head dim
#define NG 8        // groupnorm groups
#define CG 32       // channels per group
#define GN_EPS 1e-5f

// Scratch (allocation-free rule: __device__ globals)
__device__ __half g_qkvh[(size_t)NB * 3 * C * HW]; // 12 MB (fp16 qkv)
__device__ __half g_yh[(size_t)NB * C * HW];       // 4 MB (fp16 y)
__device__ float  g_A[NB * C];                     // per-(n,c) GN scale
__device__ float  g_B[NB * C];                     // per-(n,c) GN shift
__device__ float  g_part[NB * NG * 8 * 2];         // GN partial sums

typedef unsigned int uint;

// ---------------------------------------------------------------------------
// fp16 / mma helpers
// ---------------------------------------------------------------------------
__device__ __forceinline__ uint cvt_f16x2(float lo, float hi) {
    uint r;
    asm("cvt.rn.f16x2.f32 %0, %1, %2;" : "=r"(r) : "f"(hi), "f"(lo));
    return r;
}
__device__ __forceinline__ uint ex2_f16x2(uint x) {
    uint r;
    asm("ex2.approx.f16x2 %0, %1;" : "=r"(r) : "r"(x));
    return r;
}
// D = A(16x16 f16) * B(16x8 f16) + C (f32 accum)
__device__ __forceinline__ void mma16816(float& d0, float& d1, float& d2, float& d3,
                                         uint a0, uint a1, uint a2, uint a3,
                                         uint b0, uint b1,
                                         float c0, float c1, float c2, float c3) {
    asm("mma.sync.aligned.m16n8k16.row.col.f32.f16.f16.f32 "
        "{%0,%1,%2,%3}, {%4,%5,%6,%7}, {%8,%9}, {%10,%11,%12,%13};"
        : "=f"(d0), "=f"(d1), "=f"(d2), "=f"(d3)
        : "r"(a0), "r"(a1), "r"(a2), "r"(a3), "r"(b0), "r"(b1),
          "f"(c0), "f"(c1), "f"(c2), "f"(c3));
}
// D = A(16x8 f16) * B(8x8 f16) + 0 — exact k=8 (head dim), no zero padding.
__device__ __forceinline__ void mma16808(float& d0, float& d1, float& d2, float& d3,
                                         uint a0, uint a1, uint b0) {
    asm("mma.sync.aligned.m16n8k8.row.col.f32.f16.f16.f32 "
        "{%0,%1,%2,%3}, {%4,%5}, {%6}, {%7,%8,%9,%10};"
        : "=f"(d0), "=f"(d1), "=f"(d2), "=f"(d3)
        : "r"(a0), "r"(a1), "r"(b0),
          "f"(0.f), "f"(0.f), "f"(0.f), "f"(0.f));
}

// ---------------------------------------------------------------------------
// Kernel 1a: GroupNorm partial sums.  512 CTAs (8 per (n,group)).
// ---------------------------------------------------------------------------
__global__ void gn_part_kernel(const float* __restrict__ x,
                               float* __restrict__ part)
{
    const int blk = blockIdx.x;             // (n*8+g)*8 + p
    const int p = blk & 7;
    const size_t base = (size_t)(blk >> 3) * (CG * HW) + (size_t)p * (CG * HW / 8);
    const float4* xp = (const float4*)(x + base);

    float s = 0.f, ss = 0.f;
    #pragma unroll 4
    for (int i = threadIdx.x; i < (CG * HW / 8) / 4; i += 256) {
        float4 v = xp[i];
        s  += v.x + v.y + v.z + v.w;
        ss += v.x * v.x + v.y * v.y + v.z * v.z + v.w * v.w;
    }
    for (int o = 16; o > 0; o >>= 1) {
        s  += __shfl_xor_sync(0xffffffffu, s, o);
        ss += __shfl_xor_sync(0xffffffffu, ss, o);
    }
    __shared__ float rs[8], rss[8];
    const int warp = threadIdx.x >> 5, lane = threadIdx.x & 31;
    if (lane == 0) { rs[warp] = s; rss[warp] = ss; }
    __syncthreads();
    if (threadIdx.x == 0) {
        float ts = 0.f, tss = 0.f;
        #pragma unroll
        for (int i = 0; i < 8; i++) { ts += rs[i]; tss += rss[i]; }
        part[blk * 2]     = ts;
        part[blk * 2 + 1] = tss;
    }
}

// ---------------------------------------------------------------------------
// Kernel 1b: GroupNorm finalize -> per-(n,c) affine.  NB CTAs x 256 thr.
// ---------------------------------------------------------------------------
__global__ void gn_final_kernel(const float* __restrict__ part,
                                const float* __restrict__ w,
                                const float* __restrict__ b,
                                float* __restrict__ A,
                                float* __restrict__ B)
{
    const int n = blockIdx.x;
    const int c = threadIdx.x;
    const int g = c >> 5;
    float s = 0.f, ss = 0.f;
    #pragma unroll
    for (int i = 0; i < 8; i++) {
        s  += part[((n * NG + g) * 8 + i) * 2];
        ss += part[((n * NG + g) * 8 + i) * 2 + 1];
    }
    const float inv_n = 1.0f / (CG * HW);
    const float mu = s * inv_n;
    const float var = ss * inv_n - mu * mu;
    const float rstd = rsqrtf(var + GN_EPS);
    const float a = w[c] * rstd;
    A[n * C + c] = a;
    B[n * C + c] = fmaf(-mu, a, b[c]);
}

// ---------------------------------------------------------------------------
// Kernel 2/4: batched GEMM — fp16 mma, 64(o) x 128(t) x 16(k), 3 CTAs/SM.
// (validated structure, unchanged)
// ---------------------------------------------------------------------------
template <bool FUSE_GN, bool RESID, bool X_HALF, bool OUT_HALF>
__global__ void __launch_bounds__(256, 3)
gemm_h_kernel(const float* __restrict__ W,
              const void* __restrict__ Xv,
              const float* __restrict__ bias,
              const float* __restrict__ resid,
              const float* __restrict__ Ac,
              const float* __restrict__ Bc,
              void* __restrict__ Outv,
              int M)
{
    const int n  = blockIdx.x;
    const int o0 = blockIdx.y * 64;
    const int t0 = blockIdx.z * 128;

    __shared__ uint Wt[2][64][8];
    __shared__ uint Xt[2][8][128];
    __shared__ float sA[FUSE_GN ? C : 1];
    __shared__ float sB[FUSE_GN ? C : 1];

    const int tid  = threadIdx.x;
    const int warp = tid >> 5, lane = tid & 31;
    const int g  = lane >> 2, tq = lane & 3;
    const int wm = (warp & 1) << 5;
    const int wn = (warp >> 1) << 5;

    if (FUSE_GN) {
        if (tid < C) {
            sA[tid] = Ac[n * C + tid];
            sB[tid] = Bc[n * C + tid];
        }
        __syncthreads();
    }

    const int row_w = tid >> 2;
    const int cb    = (tid & 3) << 2;
    const int cp_x  = tid >> 5;
    const int tb    = lane << 2;

    const float* Wp = W + (size_t)(o0 + row_w) * C + cb;

    const float*  Xf0 = X_HALF ? nullptr
                    : (const float*)Xv + ((size_t)n * C + 2 * cp_x) * HW + t0 + tb;
    const float*  Xf1 = X_HALF ? nullptr : Xf0 + HW;
    const __half* Xh0 = X_HALF
                    ? (const __half*)Xv + ((size_t)n * C + 2 * cp_x) * HW + t0 + tb
                    : nullptr;
    const __half* Xh1 = X_HALF ? Xh0 + HW : nullptr;

    float4 w0 = *(const float4*)Wp;
    float4 x0, x1;
    uint2  ha, hb;
    if (X_HALF) { ha = *(const uint2*)Xh0; hb = *(const uint2*)Xh1; }
    else        { x0 = *(const float4*)Xf0; x1 = *(const float4*)Xf1; }

    float acc[2][4][4];
    #pragma unroll
    for (int i = 0; i < 2; i++)
        #pragma unroll
        for (int j = 0; j < 4; j++)
            #pragma unroll
            for (int r = 0; r < 4; r++) acc[i][j][r] = 0.f;

    const int swr = ((row_w >> 2) & 1) << 2;
    const int cp0 = cb >> 1;
    const int swa = ((g >> 2) & 1) << 2;
    const int xsw = (cp_x & 3) << 3;

    int buf = 0;
    for (int k0 = 0; k0 < C; k0 += 16) {
        {
            uint2 wlo = make_uint2(cvt_f16x2(w0.x, w0.y), cvt_f16x2(w0.z, w0.w));
            *(uint2*)&Wt[buf][row_w][cp0 ^ swr] = wlo;
            uint4 xu;
            if (X_HALF) {
                xu.x = __byte_perm(ha.x, hb.x, 0x5410);
                xu.y = __byte_perm(ha.x, hb.x, 0x7632);
                xu.z = __byte_perm(ha.y, hb.y, 0x5410);
                xu.w = __byte_perm(ha.y, hb.y, 0x7632);
            } else {
                if (FUSE_GN) {
                    const float aa0 = sA[k0 + 2 * cp_x],     bb0 = sB[k0 + 2 * cp_x];
                    const float aa1 = sA[k0 + 2 * cp_x + 1], bb1 = sB[k0 + 2 * cp_x + 1];
                    x0.x = fmaf(x0.x, aa0, bb0); x0.y = fmaf(x0.y, aa0, bb0);
                    x0.z = fmaf(x0.z, aa0, bb0); x0.w = fmaf(x0.w, aa0, bb0);
                    x1.x = fmaf(x1.x, aa1, bb1); x1.y = fmaf(x1.y, aa1, bb1);
                    x1.z = fmaf(x1.z, aa1, bb1); x1.w = fmaf(x1.w, aa1, bb1);
                }
                xu.x = cvt_f16x2(x0.x, x1.x);
                xu.y = cvt_f16x2(x0.y, x1.y);
                xu.z = cvt_f16x2(x0.z, x1.z);
                xu.w = cvt_f16x2(x0.w, x1.w);
            }
            *(uint4*)&Xt[buf][cp_x][tb ^ xsw] = xu;
        }
        if (k0 + 16 < C) {
            w0 = *(const float4*)(Wp + k0 + 16);
            if (X_HALF) {
                ha = *(const uint2*)(Xh0 + (size_t)(k0 + 16) * HW);
                hb = *(const uint2*)(Xh1 + (size_t)(k0 + 16) * HW);
            } else {
                x0 = *(const float4*)(Xf0 + (size_t)(k0 + 16) * HW);
                x1 = *(const float4*)(Xf1 + (size_t)(k0 + 16) * HW);
            }
        }
        __syncthreads();

        uint A[2][4];
        #pragma unroll
        for (int i = 0; i < 2; i++) {
            const uint* wr0 = Wt[buf][wm + i * 16 + g];
            const uint* wr1 = Wt[buf][wm + i * 16 + 8 + g];
            A[i][0] = wr0[tq ^ swa];
            A[i][1] = wr1[tq ^ swa];
            A[i][2] = wr0[(4 + tq) ^ swa];
            A[i][3] = wr1[(4 + tq) ^ swa];
        }
        uint Bf[4][2];
        #pragma unroll
        for (int j = 0; j < 4; j++) {
            const int col = (wn + j * 8 + g) ^ (tq << 3);
            Bf[j][0] = Xt[buf][tq][col];
            Bf[j][1] = Xt[buf][4 + tq][col];
        }
        #pragma unroll
        for (int i = 0; i < 2; i++)
            #pragma unroll
            for (int j = 0; j < 4; j++)
                mma16816(acc[i][j][0], acc[i][j][1], acc[i][j][2], acc[i][j][3],
                         A[i][0], A[i][1], A[i][2], A[i][3],
                         Bf[j][0], Bf[j][1],
                         acc[i][j][0], acc[i][j][1], acc[i][j][2], acc[i][j][3]);
        buf ^= 1;
    }

    #pragma unroll
    for (int i = 0; i < 2; i++) {
        const int r0 = o0 + wm + i * 16 + g;
        const int r1 = r0 + 8;
        const float bv0 = bias[r0];
        const float bv1 = bias[r1];
        #pragma unroll
        for (int j = 0; j < 4; j++) {
            const int col = t0 + wn + j * 8 + 2 * tq;
            const size_t idx0 = ((size_t)n * M + r0) * HW + col;
            const size_t idx1 = ((size_t)n * M + r1) * HW + col;
            float2 v0 = make_float2(acc[i][j][0] + bv0, acc[i][j][1] + bv0);
            float2 v1 = make_float2(acc[i][j][2] + bv1, acc[i][j][3] + bv1);
            if (OUT_HALF) {
                __half* Oh = (__half*)Outv;
                *(__half2*)(Oh + idx0) = __floats2half2_rn(v0.x, v0.y);
                *(__half2*)(Oh + idx1) = __floats2half2_rn(v1.x, v1.y);
            } else {
                float* Of = (float*)Outv;
                if (RESID) {
                    const float2 r0v = *(const float2*)(resid + idx0);
                    const float2 r1v = *(const float2*)(resid + idx1);
                    v0.x += r0v.x; v0.y += r0v.y;
                    v1.x += r1v.x; v1.y += r1v.y;
                }
                *(float2*)(Of + idx0) = v0;
                *(float2*)(Of + idx1) = v1;
            }
        }
    }
}

// ---------------------------------------------------------------------------
// Kernel 3: fused attention — fp16 tensor cores, k8 QK + ones-column
// denominator.  NOW: 1024 CTAs (4 per head, quarter queries each),
// 2 strips/warp, 4 CTAs/SM (64-reg cap) to keep the MUFU saturated.
// ---------------------------------------------------------------------------
__global__ void __launch_bounds__(256, 4)
attn_kernel(const __half* __restrict__ qkv, __half* __restrict__ y)
{
    __shared__ uint Kh[4096];   // [j][key^(j<<3)]  j = d-pair
    __shared__ uint Vs[4096];   // [d][kp^(d<<2)]   kp = key-pair

    const int b  = blockIdx.x;       // (n*32 + h)*4 + qq
    const int qq = b & 3;
    const int h  = (b >> 2) & 31;
    const int n  = b >> 7;
    const int tid = threadIdx.x;
    const int warp = tid >> 5, lane = tid & 31;
    const int g = lane >> 2, t = lane & 3;

    const __half* qbase = qkv + ((size_t)n * 3 * C + h * HD) * HW;
    const __half* kbase = qbase + (size_t)C * HW;
    const __half* vbase = qbase + (size_t)2 * C * HW;

    for (int idx = tid; idx < 4096; idx += 256) {
        const int j = idx >> 10, key = idx & 1023;
        __half2 hh = __halves2half2(kbase[(2 * j) * HW + key],
                                    kbase[(2 * j + 1) * HW + key]);
        Kh[(j << 10) | (key ^ (j << 3))] = *(uint*)&hh;
    }
    for (int idx = tid; idx < 4096; idx += 256) {
        const int d = idx >> 9, kp = idx & 511;
        Vs[(d << 9) | (kp ^ (d << 2))] =
            ((const uint*)(vbase + (size_t)d * HW))[kp];
    }
    __syncthreads();

    const float qscale = 0.35355339059327373f * 1.4426950408889634f;

    uint qa0[2], qa1[2];
    #pragma unroll
    for (int s = 0; s < 2; s++) {
        const int q0 = (qq << 8) + ((warp + 8 * s) << 4);
        const __half* qd0 = qbase + (2 * t) * HW;
        const __half* qd1 = qbase + (2 * t + 1) * HW;
        qa0[s] = cvt_f16x2(__half2float(qd0[q0 + g]) * qscale,
                           __half2float(qd1[q0 + g]) * qscale);
        qa1[s] = cvt_f16x2(__half2float(qd0[q0 + 8 + g]) * qscale,
                           __half2float(qd1[q0 + 8 + g]) * qscale);
    }

    float pv[2][4];
    float ls[2][4];   // ones-column mma accumulators (col0 = row sums)
    #pragma unroll
    for (int s = 0; s < 2; s++) {
        pv[s][0] = pv[s][1] = pv[s][2] = pv[s][3] = 0.f;
        ls[s][0] = ls[s][1] = ls[s][2] = ls[s][3] = 0.f;
    }

    // B-fragment of ones in column 0 only: col = lane>>2, so lanes g==0.
    const uint ones = (g == 0) ? 0x3C003C00u : 0u;

    #pragma unroll 1
    for (int kb = 0; kb < 64; kb++) {
        const int key0 = kb << 4;
        const uint kf0 = Kh[(t << 10) | ((key0 + g) ^ (t << 3))];
        const uint kf1 = Kh[(t << 10) | ((key0 + 8 + g) ^ (t << 3))];
        const int kp0 = kb << 3;
        const uint vf0 = Vs[(g << 9) | ((kp0 + t) ^ (g << 2))];
        const uint vf1 = Vs[(g << 9) | ((kp0 + 4 + t) ^ (g << 2))];

        #pragma unroll
        for (int s = 0; s < 2; s++) {
            float c0, c1, c2, c3, d0, d1, d2, d3;
            // scores via exact k=8 MMA (no zero-padded k half)
            mma16808(c0, c1, c2, c3, qa0[s], qa1[s], kf0);
            mma16808(d0, d1, d2, d3, qa0[s], qa1[s], kf1);
            const uint pa0 = ex2_f16x2(cvt_f16x2(c0, c1));
            const uint pa1 = ex2_f16x2(cvt_f16x2(c2, c3));
            const uint pa2 = ex2_f16x2(cvt_f16x2(d0, d1));
            const uint pa3 = ex2_f16x2(cvt_f16x2(d2, d3));
            // row sums via tensor pipe (col0 of D)
            mma16816(ls[s][0], ls[s][1], ls[s][2], ls[s][3],
                     pa0, pa1, pa2, pa3, ones, ones,
                     ls[s][0], ls[s][1], ls[s][2], ls[s][3]);
            // PV += P * V
            mma16816(pv[s][0], pv[s][1], pv[s][2], pv[s][3],
                     pa0, pa1, pa2, pa3, vf0, vf1,
                     pv[s][0], pv[s][1], pv[s][2], pv[s][3]);
        }
    }

    __half* yb = y + ((size_t)n * C + h * HD) * HW;
    #pragma unroll
    for (int s = 0; s < 2; s++) {
        // row sums live on lanes tq==0 (col 0); broadcast within each row group
        const float la = __shfl_sync(0xffffffffu, ls[s][0], lane & 28);
        const float lb = __shfl_sync(0xffffffffu, ls[s][2], lane & 28);
        const float inva = __fdividef(1.0f, la);
        const float invb = __fdividef(1.0f, lb);
        const int q0 = (qq << 8) + ((warp + 8 * s) << 4);
        yb[(2 * t) * HW + q0 + g]         = __float2half(pv[s][0] * inva);
        yb[(2 * t + 1) * HW + q0 + g]     = __float2half(pv[s][1] * inva);
        yb[(2 * t) * HW + q0 + 8 + g]     = __float2half(pv[s][2] * invb);
        yb[(2 * t + 1) * HW + q0 + 8 + g] = __float2half(pv[s][3] * invb);
    }
}

// ---------------------------------------------------------------------------
extern "C" void kernel_launch(void* const* d_in, const int* in_sizes, int n_in,
                              void* d_out, int out_size)
{
    const float* x     = (const float*)d_in[0];
    const float* gn_w  = (const float*)d_in[1];
    const float* gn_b  = (const float*)d_in[2];
    const float* qkv_w = (const float*)d_in[3];
    const float* qkv_b = (const float*)d_in[4];
    const float* out_w = (const float*)d_in[5];
    const float* out_b = (const float*)d_in[6];
    float* out = (float*)d_out;

    __half *qkvh, *yh;
    float *A, *B, *part;
    cudaGetSymbolAddress((void**)&qkvh, g_qkvh);
    cudaGetSymbolAddress((void**)&yh,   g_yh);
    cudaGetSymbolAddress((void**)&A,    g_A);
    cudaGetSymbolAddress((void**)&B,    g_B);
    cudaGetSymbolAddress((void**)&part, g_part);

    // 1. GroupNorm stats: full-chip partial reduce + tiny finalize
    gn_part_kernel<<<NB * NG * 8, 256>>>(x, part);
    gn_final_kernel<<<NB, 256>>>(part, gn_w, gn_b, A, B);

    // 2. QKV projection (fp16 mma) with fused GN; fp16 output
    {
        dim3 grid(NB, (3 * C) / 64, HW / 128);
        gemm_h_kernel<true, false, false, true><<<grid, 256>>>(
            qkv_w, x, qkv_b, nullptr, A, B, qkvh, 3 * C);
    }

    // 3. Attention: 1024 CTAs (4 per head), 4 CTAs/SM
    attn_kernel<<<NB * NH * 4, 256>>>(qkvh, yh);

    // 4. Output projection (fp16 mma, half X) + bias + residual, fp32 out
    {
        dim3 grid(NB, C / 64, HW / 128);
        gemm_h_kernel<false, true, true, false><<<grid, 256>>>(
            out_w, yh, out_b, x, nullptr, nullptr, out, C);
    }
}

// round 17
// speedup vs baseline: 1.4891x; 1.0212x over previous
#include <cuda_runtime.h>
#include <cuda_bf16.h>
#include <cuda_fp16.h>
#include <math.h>

// Problem constants
#define NB 8        // batch
#define C 256       // channels
#define HW 1024     // 32*32
#define NH 32       // heads
#define HD 8        // head dim
#define NG 8        // groupnorm groups
#define CG 32       // channels per group
#define GN_EPS 1e-5f

// Scratch (allocation-free rule: __device__ globals)
__device__ __half g_qkvh[(size_t)NB * 3 * C * HW]; // 12 MB (fp16 qkv)
__device__ __half g_yh[(size_t)NB * C * HW];       // 4 MB (fp16 y)
__device__ __half g_qkvwh[3 * C * C];              // fp16 qkv weights
__device__ __half g_outwh[C * C];                  // fp16 out weights
__device__ float  g_A[NB * C];                     // per-(n,c) GN scale
__device__ float  g_B[NB * C];                     // per-(n,c) GN shift
__device__ float  g_part[NB * NG * 8 * 2];         // GN partial sums

typedef unsigned int uint;

// ---------------------------------------------------------------------------
// fp16 / mma helpers
// ---------------------------------------------------------------------------
__device__ __forceinline__ uint cvt_f16x2(float lo, float hi) {
    uint r;
    asm("cvt.rn.f16x2.f32 %0, %1, %2;" : "=r"(r) : "f"(hi), "f"(lo));
    return r;
}
__device__ __forceinline__ uint ex2_f16x2(uint x) {
    uint r;
    asm("ex2.approx.f16x2 %0, %1;" : "=r"(r) : "r"(x));
    return r;
}
// D = A(16x16 f16) * B(16x8 f16) + C (f32 accum)
__device__ __forceinline__ void mma16816(float& d0, float& d1, float& d2, float& d3,
                                         uint a0, uint a1, uint a2, uint a3,
                                         uint b0, uint b1,
                                         float c0, float c1, float c2, float c3) {
    asm("mma.sync.aligned.m16n8k16.row.col.f32.f16.f16.f32 "
        "{%0,%1,%2,%3}, {%4,%5,%6,%7}, {%8,%9}, {%10,%11,%12,%13};"
        : "=f"(d0), "=f"(d1), "=f"(d2), "=f"(d3)
        : "r"(a0), "r"(a1), "r"(a2), "r"(a3), "r"(b0), "r"(b1),
          "f"(c0), "f"(c1), "f"(c2), "f"(c3));
}
// D = A(16x8 f16) * B(8x8 f16) + 0 — exact k=8 (head dim), no zero padding.
__device__ __forceinline__ void mma16808(float& d0, float& d1, float& d2, float& d3,
                                         uint a0, uint a1, uint b0) {
    asm("mma.sync.aligned.m16n8k8.row.col.f32.f16.f16.f32 "
        "{%0,%1,%2,%3}, {%4,%5}, {%6}, {%7,%8,%9,%10};"
        : "=f"(d0), "=f"(d1), "=f"(d2), "=f"(d3)
        : "r"(a0), "r"(a1), "r"(b0),
          "f"(0.f), "f"(0.f), "f"(0.f), "f"(0.f));
}

// ---------------------------------------------------------------------------
// Kernel 0: one-time weight conversion fp32 -> fp16 (both matrices).
// ---------------------------------------------------------------------------
__global__ void wconv_kernel(const float* __restrict__ qw,
                             const float* __restrict__ ow,
                             __half* __restrict__ qwh,
                             __half* __restrict__ owh)
{
    const int i = (blockIdx.x * 256 + threadIdx.x) * 4;   // 4 elems/thread
    const int NQ = 3 * C * C;                             // 196608
    if (i < NQ) {
        float4 v = *(const float4*)(qw + i);
        *(uint2*)(qwh + i) = make_uint2(cvt_f16x2(v.x, v.y), cvt_f16x2(v.z, v.w));
    } else {
        const int j = i - NQ;
        float4 v = *(const float4*)(ow + j);
        *(uint2*)(owh + j) = make_uint2(cvt_f16x2(v.x, v.y), cvt_f16x2(v.z, v.w));
    }
}

// ---------------------------------------------------------------------------
// Kernel 1a: GroupNorm partial sums.  512 CTAs (8 per (n,group)).
// ---------------------------------------------------------------------------
__global__ void gn_part_kernel(const float* __restrict__ x,
                               float* __restrict__ part)
{
    const int blk = blockIdx.x;             // (n*8+g)*8 + p
    const int p = blk & 7;
    const size_t base = (size_t)(blk >> 3) * (CG * HW) + (size_t)p * (CG * HW / 8);
    const float4* xp = (const float4*)(x + base);

    float s = 0.f, ss = 0.f;
    #pragma unroll 4
    for (int i = threadIdx.x; i < (CG * HW / 8) / 4; i += 256) {
        float4 v = xp[i];
        s  += v.x + v.y + v.z + v.w;
        ss += v.x * v.x + v.y * v.y + v.z * v.z + v.w * v.w;
    }
    for (int o = 16; o > 0; o >>= 1) {
        s  += __shfl_xor_sync(0xffffffffu, s, o);
        ss += __shfl_xor_sync(0xffffffffu, ss, o);
    }
    __shared__ float rs[8], rss[8];
    const int warp = threadIdx.x >> 5, lane = threadIdx.x & 31;
    if (lane == 0) { rs[warp] = s; rss[warp] = ss; }
    __syncthreads();
    if (threadIdx.x == 0) {
        float ts = 0.f, tss = 0.f;
        #pragma unroll
        for (int i = 0; i < 8; i++) { ts += rs[i]; tss += rss[i]; }
        part[blk * 2]     = ts;
        part[blk * 2 + 1] = tss;
    }
}

// ---------------------------------------------------------------------------
// Kernel 1b: GroupNorm finalize -> per-(n,c) affine.  NB CTAs x 256 thr.
// ---------------------------------------------------------------------------
__global__ void gn_final_kernel(const float* __restrict__ part,
                                const float* __restrict__ w,
                                const float* __restrict__ b,
                                float* __restrict__ A,
                                float* __restrict__ B)
{
    const int n = blockIdx.x;
    const int c = threadIdx.x;
    const int g = c >> 5;
    float s = 0.f, ss = 0.f;
    #pragma unroll
    for (int i = 0; i < 8; i++) {
        s  += part[((n * NG + g) * 8 + i) * 2];
        ss += part[((n * NG + g) * 8 + i) * 2 + 1];
    }
    const float inv_n = 1.0f / (CG * HW);
    const float mu = s * inv_n;
    const float var = ss * inv_n - mu * mu;
    const float rstd = rsqrtf(var + GN_EPS);
    const float a = w[c] * rstd;
    A[n * C + c] = a;
    B[n * C + c] = fmaf(-mu, a, b[c]);
}

// ---------------------------------------------------------------------------
// Kernel 2/4: batched GEMM — fp16 mma, 64(o) x 128(t) x 16(k), 3 CTAs/SM.
// W is pre-converted fp16: loader = direct uint2 LDG -> uint2 STS (k-pairs
// are consecutive in memory; no cvt, no PRMT).
// ---------------------------------------------------------------------------
template <bool FUSE_GN, bool RESID, bool X_HALF, bool OUT_HALF>
__global__ void __launch_bounds__(256, 3)
gemm_h_kernel(const __half* __restrict__ W,
              const void* __restrict__ Xv,
              const float* __restrict__ bias,
              const float* __restrict__ resid,
              const float* __restrict__ Ac,
              const float* __restrict__ Bc,
              void* __restrict__ Outv,
              int M)
{
    const int n  = blockIdx.x;
    const int o0 = blockIdx.y * 64;
    const int t0 = blockIdx.z * 128;

    __shared__ uint Wt[2][64][8];
    __shared__ uint Xt[2][8][128];
    __shared__ float sA[FUSE_GN ? C : 1];
    __shared__ float sB[FUSE_GN ? C : 1];

    const int tid  = threadIdx.x;
    const int warp = tid >> 5, lane = tid & 31;
    const int g  = lane >> 2, tq = lane & 3;
    const int wm = (warp & 1) << 5;
    const int wn = (warp >> 1) << 5;

    if (FUSE_GN) {
        if (tid < C) {
            sA[tid] = Ac[n * C + tid];
            sB[tid] = Bc[n * C + tid];
        }
        __syncthreads();
    }

    const int row_w = tid >> 2;
    const int cb    = (tid & 3) << 2;
    const int cp_x  = tid >> 5;
    const int tb    = lane << 2;

    const __half* Wp = W + (size_t)(o0 + row_w) * C + cb;

    const float*  Xf0 = X_HALF ? nullptr
                    : (const float*)Xv + ((size_t)n * C + 2 * cp_x) * HW + t0 + tb;
    const float*  Xf1 = X_HALF ? nullptr : Xf0 + HW;
    const __half* Xh0 = X_HALF
                    ? (const __half*)Xv + ((size_t)n * C + 2 * cp_x) * HW + t0 + tb
                    : nullptr;
    const __half* Xh1 = X_HALF ? Xh0 + HW : nullptr;

    uint2 hw = *(const uint2*)Wp;
    float4 x0, x1;
    uint2  ha, hb;
    if (X_HALF) { ha = *(const uint2*)Xh0; hb = *(const uint2*)Xh1; }
    else        { x0 = *(const float4*)Xf0; x1 = *(const float4*)Xf1; }

    float acc[2][4][4];
    #pragma unroll
    for (int i = 0; i < 2; i++)
        #pragma unroll
        for (int j = 0; j < 4; j++)
            #pragma unroll
            for (int r = 0; r < 4; r++) acc[i][j][r] = 0.f;

    const int swr = ((row_w >> 2) & 1) << 2;
    const int cp0 = cb >> 1;
    const int swa = ((g >> 2) & 1) << 2;
    const int xsw = (cp_x & 3) << 3;

    int buf = 0;
    for (int k0 = 0; k0 < C; k0 += 16) {
        {
            *(uint2*)&Wt[buf][row_w][cp0 ^ swr] = hw;
            uint4 xu;
            if (X_HALF) {
                xu.x = __byte_perm(ha.x, hb.x, 0x5410);
                xu.y = __byte_perm(ha.x, hb.x, 0x7632);
                xu.z = __byte_perm(ha.y, hb.y, 0x5410);
                xu.w = __byte_perm(ha.y, hb.y, 0x7632);
            } else {
                if (FUSE_GN) {
                    const float aa0 = sA[k0 + 2 * cp_x],     bb0 = sB[k0 + 2 * cp_x];
                    const float aa1 = sA[k0 + 2 * cp_x + 1], bb1 = sB[k0 + 2 * cp_x + 1];
                    x0.x = fmaf(x0.x, aa0, bb0); x0.y = fmaf(x0.y, aa0, bb0);
                    x0.z = fmaf(x0.z, aa0, bb0); x0.w = fmaf(x0.w, aa0, bb0);
                    x1.x = fmaf(x1.x, aa1, bb1); x1.y = fmaf(x1.y, aa1, bb1);
                    x1.z = fmaf(x1.z, aa1, bb1); x1.w = fmaf(x1.w, aa1, bb1);
                }
                xu.x = cvt_f16x2(x0.x, x1.x);
                xu.y = cvt_f16x2(x0.y, x1.y);
                xu.z = cvt_f16x2(x0.z, x1.z);
                xu.w = cvt_f16x2(x0.w, x1.w);
            }
            *(uint4*)&Xt[buf][cp_x][tb ^ xsw] = xu;
        }
        if (k0 + 16 < C) {
            hw = *(const uint2*)(Wp + k0 + 16);
            if (X_HALF) {
                ha = *(const uint2*)(Xh0 + (size_t)(k0 + 16) * HW);
                hb = *(const uint2*)(Xh1 + (size_t)(k0 + 16) * HW);
            } else {
                x0 = *(const float4*)(Xf0 + (size_t)(k0 + 16) * HW);
                x1 = *(const float4*)(Xf1 + (size_t)(k0 + 16) * HW);
            }
        }
        __syncthreads();

        uint A[2][4];
        #pragma unroll
        for (int i = 0; i < 2; i++) {
            const uint* wr0 = Wt[buf][wm + i * 16 + g];
            const uint* wr1 = Wt[buf][wm + i * 16 + 8 + g];
            A[i][0] = wr0[tq ^ swa];
            A[i][1] = wr1[tq ^ swa];
            A[i][2] = wr0[(4 + tq) ^ swa];
            A[i][3] = wr1[(4 + tq) ^ swa];
        }
        uint Bf[4][2];
        #pragma unroll
        for (int j = 0; j < 4; j++) {
            const int col = (wn + j * 8 + g) ^ (tq << 3);
            Bf[j][0] = Xt[buf][tq][col];
            Bf[j][1] = Xt[buf][4 + tq][col];
        }
        #pragma unroll
        for (int i = 0; i < 2; i++)
            #pragma unroll
            for (int j = 0; j < 4; j++)
                mma16816(acc[i][j][0], acc[i][j][1], acc[i][j][2], acc[i][j][3],
                         A[i][0], A[i][1], A[i][2], A[i][3],
                         Bf[j][0], Bf[j][1],
                         acc[i][j][0], acc[i][j][1], acc[i][j][2], acc[i][j][3]);
        buf ^= 1;
    }

    #pragma unroll
    for (int i = 0; i < 2; i++) {
        const int r0 = o0 + wm + i * 16 + g;
        const int r1 = r0 + 8;
        const float bv0 = bias[r0];
        const float bv1 = bias[r1];
        #pragma unroll
        for (int j = 0; j < 4; j++) {
            const int col = t0 + wn + j * 8 + 2 * tq;
            const size_t idx0 = ((size_t)n * M + r0) * HW + col;
            const size_t idx1 = ((size_t)n * M + r1) * HW + col;
            float2 v0 = make_float2(acc[i][j][0] + bv0, acc[i][j][1] + bv0);
            float2 v1 = make_float2(acc[i][j][2] + bv1, acc[i][j][3] + bv1);
            if (OUT_HALF) {
                __half* Oh = (__half*)Outv;
                *(__half2*)(Oh + idx0) = __floats2half2_rn(v0.x, v0.y);
                *(__half2*)(Oh + idx1) = __floats2half2_rn(v1.x, v1.y);
            } else {
                float* Of = (float*)Outv;
                if (RESID) {
                    const float2 r0v = *(const float2*)(resid + idx0);
                    const float2 r1v = *(const float2*)(resid + idx1);
                    v0.x += r0v.x; v0.y += r0v.y;
                    v1.x += r1v.x; v1.y += r1v.y;
                }
                *(float2*)(Of + idx0) = v0;
                *(float2*)(Of + idx1) = v1;
            }
        }
    }
}

// ---------------------------------------------------------------------------
// Kernel 3: fused attention — fp16 tensor cores, k8 QK + ones-column
// denominator.  1024 CTAs (4 per head), 4 CTAs/SM.  (validated; MUFU-bound)
// ---------------------------------------------------------------------------
__global__ void __launch_bounds__(256, 4)
attn_kernel(const __half* __restrict__ qkv, __half* __restrict__ y)
{
    __shared__ uint Kh[4096];   // [j][key^(j<<3)]  j = d-pair
    __shared__ uint Vs[4096];   // [d][kp^(d<<2)]   kp = key-pair

    const int b  = blockIdx.x;       // (n*32 + h)*4 + qq
    const int qq = b & 3;
    const int h  = (b >> 2) & 31;
    const int n  = b >> 7;
    const int tid = threadIdx.x;
    const int warp = tid >> 5, lane = tid & 31;
    const int g = lane >> 2, t = lane & 3;

    const __half* qbase = qkv + ((size_t)n * 3 * C + h * HD) * HW;
    const __half* kbase = qbase + (size_t)C * HW;
    const __half* vbase = qbase + (size_t)2 * C * HW;

    for (int idx = tid; idx < 4096; idx += 256) {
        const int j = idx >> 10, key = idx & 1023;
        __half2 hh = __halves2half2(kbase[(2 * j) * HW + key],
                                    kbase[(2 * j + 1) * HW + key]);
        Kh[(j << 10) | (key ^ (j << 3))] = *(uint*)&hh;
    }
    for (int idx = tid; idx < 4096; idx += 256) {
        const int d = idx >> 9, kp = idx & 511;
        Vs[(d << 9) | (kp ^ (d << 2))] =
            ((const uint*)(vbase + (size_t)d * HW))[kp];
    }
    __syncthreads();

    const float qscale = 0.35355339059327373f * 1.4426950408889634f;

    uint qa0[2], qa1[2];
    #pragma unroll
    for (int s = 0; s < 2; s++) {
        const int q0 = (qq << 8) + ((warp + 8 * s) << 4);
        const __half* qd0 = qbase + (2 * t) * HW;
        const __half* qd1 = qbase + (2 * t + 1) * HW;
        qa0[s] = cvt_f16x2(__half2float(qd0[q0 + g]) * qscale,
                           __half2float(qd1[q0 + g]) * qscale);
        qa1[s] = cvt_f16x2(__half2float(qd0[q0 + 8 + g]) * qscale,
                           __half2float(qd1[q0 + 8 + g]) * qscale);
    }

    float pv[2][4];
    float ls[2][4];   // ones-column mma accumulators (col0 = row sums)
    #pragma unroll
    for (int s = 0; s < 2; s++) {
        pv[s][0] = pv[s][1] = pv[s][2] = pv[s][3] = 0.f;
        ls[s][0] = ls[s][1] = ls[s][2] = ls[s][3] = 0.f;
    }

    // B-fragment of ones in column 0 only: col = lane>>2, so lanes g==0.
    const uint ones = (g == 0) ? 0x3C003C00u : 0u;

    #pragma unroll 1
    for (int kb = 0; kb < 64; kb++) {
        const int key0 = kb << 4;
        const uint kf0 = Kh[(t << 10) | ((key0 + g) ^ (t << 3))];
        const uint kf1 = Kh[(t << 10) | ((key0 + 8 + g) ^ (t << 3))];
        const int kp0 = kb << 3;
        const uint vf0 = Vs[(g << 9) | ((kp0 + t) ^ (g << 2))];
        const uint vf1 = Vs[(g << 9) | ((kp0 + 4 + t) ^ (g << 2))];

        #pragma unroll
        for (int s = 0; s < 2; s++) {
            float c0, c1, c2, c3, d0, d1, d2, d3;
            mma16808(c0, c1, c2, c3, qa0[s], qa1[s], kf0);
            mma16808(d0, d1, d2, d3, qa0[s], qa1[s], kf1);
            const uint pa0 = ex2_f16x2(cvt_f16x2(c0, c1));
            const uint pa1 = ex2_f16x2(cvt_f16x2(c2, c3));
            const uint pa2 = ex2_f16x2(cvt_f16x2(d0, d1));
            const uint pa3 = ex2_f16x2(cvt_f16x2(d2, d3));
            mma16816(ls[s][0], ls[s][1], ls[s][2], ls[s][3],
                     pa0, pa1, pa2, pa3, ones, ones,
                     ls[s][0], ls[s][1], ls[s][2], ls[s][3]);
            mma16816(pv[s][0], pv[s][1], pv[s][2], pv[s][3],
                     pa0, pa1, pa2, pa3, vf0, vf1,
                     pv[s][0], pv[s][1], pv[s][2], pv[s][3]);
        }
    }

    __half* yb = y + ((size_t)n * C + h * HD) * HW;
    #pragma unroll
    for (int s = 0; s < 2; s++) {
        const float la = __shfl_sync(0xffffffffu, ls[s][0], lane & 28);
        const float lb = __shfl_sync(0xffffffffu, ls[s][2], lane & 28);
        const float inva = __fdividef(1.0f, la);
        const float invb = __fdividef(1.0f, lb);
        const int q0 = (qq << 8) + ((warp + 8 * s) << 4);
        yb[(2 * t) * HW + q0 + g]         = __float2half(pv[s][0] * inva);
        yb[(2 * t + 1) * HW + q0 + g]     = __float2half(pv[s][1] * inva);
        yb[(2 * t) * HW + q0 + 8 + g]     = __float2half(pv[s][2] * invb);
        yb[(2 * t + 1) * HW + q0 + 8 + g] = __float2half(pv[s][3] * invb);
    }
}

// ---------------------------------------------------------------------------
extern "C" void kernel_launch(void* const* d_in, const int* in_sizes, int n_in,
                              void* d_out, int out_size)
{
    const float* x     = (const float*)d_in[0];
    const float* gn_w  = (const float*)d_in[1];
    const float* gn_b  = (const float*)d_in[2];
    const float* qkv_w = (const float*)d_in[3];
    const float* qkv_b = (const float*)d_in[4];
    const float* out_w = (const float*)d_in[5];
    const float* out_b = (const float*)d_in[6];
    float* out = (float*)d_out;

    __half *qkvh, *yh, *qwh, *owh;
    float *A, *B, *part;
    cudaGetSymbolAddress((void**)&qkvh, g_qkvh);
    cudaGetSymbolAddress((void**)&yh,   g_yh);
    cudaGetSymbolAddress((void**)&qwh,  g_qkvwh);
    cudaGetSymbolAddress((void**)&owh,  g_outwh);
    cudaGetSymbolAddress((void**)&A,    g_A);
    cudaGetSymbolAddress((void**)&B,    g_B);
    cudaGetSymbolAddress((void**)&part, g_part);

    // 0. Weight conversion fp32 -> fp16 (both matrices; 4*256*256 elems total)
    wconv_kernel<<<(4 * C * C) / 1024, 256>>>(qkv_w, out_w, qwh, owh);

    // 1. GroupNorm stats: full-chip partial reduce + tiny finalize
    gn_part_kernel<<<NB * NG * 8, 256>>>(x, part);
    gn_final_kernel<<<NB, 256>>>(part, gn_w, gn_b, A, B);

    // 2. QKV projection (fp16 mma, fp16 W) with fused GN; fp16 output
    {
        dim3 grid(NB, (3 * C) / 64, HW / 128);
        gemm_h_kernel<true, false, false, true><<<grid, 256>>>(
            qwh, x, qkv_b, nullptr, A, B, qkvh, 3 * C);
    }

    // 3. Attention: 1024 CTAs (4 per head), 4 CTAs/SM
    attn_kernel<<<NB * NH * 4, 256>>>(qkvh, yh);

    // 4. Output projection (fp16 mma, fp16 W, half X) + bias + residual
    {
        dim3 grid(NB, C / 64, HW / 128);
        gemm_h_kernel<false, true, true, false><<<grid, 256>>>(
            owh, yh, out_b, x, nullptr, nullptr, out, C);
    }
}